// round 3
// baseline (speedup 1.0000x reference)
#include <cuda_runtime.h>
#include <cstdint>

// Problem dims (fixed by the dataset)
#define BB 256
#define TT 256
#define DD 128
#define HH 256
#define NROWS (BB*TT)          // 65536

// Scratch: h1 (post-LN, pre-LIF) [B,T,H]
__device__ __align__(16) float g_h1[(size_t)NROWS * HH];   // 67 MB

// ---------------------------------------------------------------------------
// packed fp32x2 helpers (sm_10x FFMA2 — PTX-only, ptxas never auto-emits)
// ---------------------------------------------------------------------------
__device__ __forceinline__ unsigned long long pack2(float lo, float hi) {
    unsigned long long p;
    asm("mov.b64 %0, {%1, %2};" : "=l"(p) : "f"(lo), "f"(hi));
    return p;
}
__device__ __forceinline__ void unpack2(unsigned long long p, float& lo, float& hi) {
    asm("mov.b64 {%0, %1}, %2;" : "=f"(lo), "=f"(hi) : "l"(p));
}
__device__ __forceinline__ void fma2(unsigned long long& acc,
                                     unsigned long long a, unsigned long long b) {
    asm("fma.rn.f32x2 %0, %1, %2, %0;" : "+l"(acc) : "l"(a), "l"(b));
}

// ---------------------------------------------------------------------------
// GEMM1 + bias + LayerNorm(H):  g_h1[row][h] = LN( dot(x[row,:], W1[h,:]) + b1 )
// Block: 64 rows. W1 staged k-major [128][256]; x staged DUPLICATED {v,v}
// pairs so the inner loop is pure LDS.64 + FFMA2 (no pack MOVs).
// Warp owns 8 rows; lane owns h pairs {2l,2l+1}+64j (j<4) -> acc[4][8].
// ---------------------------------------------------------------------------
#define G1_SMEM_FLOATS (128*256 + 64*256)
__global__ __launch_bounds__(256, 1)
void gemm1_ln_kernel(const float* __restrict__ x,
                     const float* __restrict__ W1,
                     const float* __restrict__ b1,
                     const float* __restrict__ g1,
                     const float* __restrict__ be1)
{
    extern __shared__ float sm[];
    float* wst = sm;                 // [k=128][h=256]
    float* xs2 = sm + 128*256;       // [r=64][2k dup = 256]

    const int tid = threadIdx.x;
    const int rowBase = blockIdx.x * 64;

    // Stage W1 transposed: thread tid owns h=tid, streams its gmem row.
    {
        const float4* W4 = (const float4*)W1;       // [h][k4] 256x32
        const int h = tid;
        #pragma unroll
        for (int i = 0; i < 32; i++) {
            float4 v = W4[h*32 + i];
            int k = i*4;
            wst[(k+0)*256 + h] = v.x;
            wst[(k+1)*256 + h] = v.y;
            wst[(k+2)*256 + h] = v.z;
            wst[(k+3)*256 + h] = v.w;
        }
    }
    // Stage x rows duplicated: xs2[r*256 + 2k + {0,1}] = x[r][k]
    {
        const float2* X2 = (const float2*)(x + (size_t)rowBase * DD);  // 4096 float2
        #pragma unroll
        for (int i = 0; i < 16; i++) {
            int s2 = tid + i*256;            // float2 index: r = s2>>6, kp = s2&63
            float2 v = X2[s2];
            int r = s2 >> 6, k = (s2 & 63) * 2;
            *(float2*)(xs2 + r*256 + 2*k)     = make_float2(v.x, v.x);
            *(float2*)(xs2 + r*256 + 2*k + 2) = make_float2(v.y, v.y);
        }
    }
    __syncthreads();

    const int lane = tid & 31;
    const int wrp  = tid >> 5;
    const int rowOff = wrp * 8;

    unsigned long long acc[4][8];
    #pragma unroll
    for (int j = 0; j < 4; j++) {
        float2 bb = *(const float2*)(b1 + 2*lane + 64*j);
        unsigned long long bp = pack2(bb.x, bb.y);
        #pragma unroll
        for (int r = 0; r < 8; r++) acc[j][r] = bp;
    }

    #pragma unroll 2
    for (int k = 0; k < 128; k++) {
        unsigned long long wv[4];
        #pragma unroll
        for (int j = 0; j < 4; j++)
            wv[j] = *(const unsigned long long*)(wst + k*256 + 2*lane + 64*j);
        #pragma unroll
        for (int r = 0; r < 8; r++) {
            unsigned long long xp =
                *(const unsigned long long*)(xs2 + (rowOff + r)*256 + 2*k);
            #pragma unroll
            for (int j = 0; j < 4; j++) fma2(acc[j][r], wv[j], xp);
        }
    }

    // Warp-local LayerNorm per row (256 h spread over 32 lanes x 8 values)
    #pragma unroll
    for (int r = 0; r < 8; r++) {
        float v[8];
        #pragma unroll
        for (int j = 0; j < 4; j++) unpack2(acc[j][r], v[2*j], v[2*j+1]);
        float sum = 0.f, sq = 0.f;
        #pragma unroll
        for (int i = 0; i < 8; i++) { sum += v[i]; sq += v[i]*v[i]; }
        #pragma unroll
        for (int o = 16; o; o >>= 1) {
            sum += __shfl_xor_sync(0xffffffffu, sum, o);
            sq  += __shfl_xor_sync(0xffffffffu, sq,  o);
        }
        float mean = sum * (1.f/256.f);
        float var  = fmaxf(sq * (1.f/256.f) - mean*mean, 0.f) + 1e-5f;
        float inv  = rsqrtf(var);
        inv = inv * (1.5f - 0.5f * var * inv * inv);   // Newton -> fp32-exact rsqrt
        float* op = g_h1 + (size_t)(rowBase + rowOff + r) * HH;
        #pragma unroll
        for (int j = 0; j < 4; j++) {
            int h = 2*lane + 64*j;
            float2 gg = *(const float2*)(g1 + h);
            float2 bb = *(const float2*)(be1 + h);
            float2 o;
            o.x = (v[2*j]   - mean) * inv * gg.x + bb.x;
            o.y = (v[2*j+1] - mean) * inv * gg.y + bb.y;
            *(float2*)(op + h) = o;
        }
    }
}

// ---------------------------------------------------------------------------
// Fused: LIF1 -> GEMM2 -> LN(D) -> LIF2 -> +residual -> out
// Block = one batch b (256 t rows), 256 threads, chunked by CH=32 t.
// Spikes never touch gmem: h1 chunk staged -> LIF1 writes duplicated {s,s}
// spike pairs -> GEMM2 (FFMA2) -> LN -> LIF2 (aliased buffer) -> out.
// ---------------------------------------------------------------------------
#define CH 32
#define NCH (TT/CH)            // 8
#define FB_SMEM_FLOATS (256*128 + CH*256 + CH*512)   // wst + h1s + ss2 (os aliases ss2)
__global__ __launch_bounds__(256, 1)
void fused2_kernel(const float* __restrict__ x,
                   const float* __restrict__ W2,
                   const float* __restrict__ b2,
                   const float* __restrict__ g2,
                   const float* __restrict__ be2,
                   float* __restrict__ out)
{
    extern __shared__ float sm[];
    float* wst = sm;                     // [h=256][d=128] k-major
    float* h1s = sm + 256*128;           // [CH][256]
    float* ss2 = h1s + CH*256;           // [CH][256h x2 dup]; os aliases this
    float* os  = ss2;                    // [CH][128]

    const int tid  = threadIdx.x;
    const int b    = blockIdx.x;
    const int lane = tid & 31;
    const int wrp  = tid >> 5;
    const int rowOff = wrp * 4;          // 8 warps x 4 rows = 32 rows/chunk

    const float* h1base = g_h1 + (size_t)b * (TT * HH);

    // Prefetch chunk 0 into registers (overlaps with W2 staging)
    float4 pf[8];
    {
        const float4* H4 = (const float4*)h1base;
        #pragma unroll
        for (int i = 0; i < 8; i++) pf[i] = H4[tid + i*256];
    }

    // Stage W2 k-major: W2 gmem is [d=128][h=256] row-major.
    {
        const float4* W4 = (const float4*)W2;   // [d][h4] 128x64
        const int d = tid & 127, half = tid >> 7;
        #pragma unroll
        for (int i = 0; i < 32; i++) {
            float4 v = W4[d*64 + half*32 + i];
            int h = (half*32 + i) * 4;
            wst[(h+0)*128 + d] = v.x;
            wst[(h+1)*128 + d] = v.y;
            wst[(h+2)*128 + d] = v.z;
            wst[(h+3)*128 + d] = v.w;
        }
    }

    // bias pairs (hoisted)
    unsigned long long bp[2];
    #pragma unroll
    for (int j = 0; j < 2; j++) {
        float2 bb = *(const float2*)(b2 + 2*lane + 64*j);
        bp[j] = pack2(bb.x, bb.y);
    }
    // LN params for LIF/LN phases
    float v1 = 0.f, v2 = 0.f;

    const size_t xbase = (size_t)b * (TT * DD);

    for (int c = 0; c < NCH; c++) {
        // write prefetched chunk into h1s
        #pragma unroll
        for (int i = 0; i < 8; i++)
            *(float4*)(h1s + 4*(tid + i*256)) = pf[i];
        __syncthreads();

        // LIF1: thread owns h=tid; write duplicated spike pairs
        {
            float v = v1;
            #pragma unroll
            for (int t = 0; t < CH; t++) {
                float cc = h1s[t*256 + tid];
                float hm = v + (cc - v) * 0.5f;
                float s  = (hm >= 1.f) ? 1.f : 0.f;
                v = (hm >= 1.f) ? 0.f : hm;
                *(float2*)(ss2 + t*512 + 2*tid) = make_float2(s, s);
            }
            v1 = v;
        }
        // prefetch next chunk (hidden behind GEMM)
        if (c + 1 < NCH) {
            const float4* H4 = (const float4*)(h1base + (size_t)(c+1) * CH * HH);
            #pragma unroll
            for (int i = 0; i < 8; i++) pf[i] = H4[tid + i*256];
        }
        __syncthreads();

        // GEMM2: 32 rows x 128 d, k over 256 h
        unsigned long long acc[2][4];
        #pragma unroll
        for (int j = 0; j < 2; j++)
            #pragma unroll
            for (int r = 0; r < 4; r++) acc[j][r] = bp[j];

        #pragma unroll 2
        for (int k = 0; k < 256; k++) {
            unsigned long long wv0 = *(const unsigned long long*)(wst + k*128 + 2*lane);
            unsigned long long wv1 = *(const unsigned long long*)(wst + k*128 + 2*lane + 64);
            #pragma unroll
            for (int r = 0; r < 4; r++) {
                unsigned long long sp =
                    *(const unsigned long long*)(ss2 + (rowOff + r)*512 + 2*k);
                fma2(acc[0][r], wv0, sp);
                fma2(acc[1][r], wv1, sp);
            }
        }
        __syncthreads();   // all warps done reading ss2 before os (alias) writes

        // LayerNorm over D=128 per row, warp-local; write to os (aliases ss2)
        #pragma unroll
        for (int r = 0; r < 4; r++) {
            float v[4];
            #pragma unroll
            for (int j = 0; j < 2; j++) unpack2(acc[j][r], v[2*j], v[2*j+1]);
            float sum = 0.f, sq = 0.f;
            #pragma unroll
            for (int i = 0; i < 4; i++) { sum += v[i]; sq += v[i]*v[i]; }
            #pragma unroll
            for (int o = 16; o; o >>= 1) {
                sum += __shfl_xor_sync(0xffffffffu, sum, o);
                sq  += __shfl_xor_sync(0xffffffffu, sq,  o);
            }
            float mean = sum * (1.f/128.f);
            float var  = fmaxf(sq * (1.f/128.f) - mean*mean, 0.f) + 1e-5f;
            float inv  = rsqrtf(var);
            inv = inv * (1.5f - 0.5f * var * inv * inv);
            int row = rowOff + r;
            #pragma unroll
            for (int j = 0; j < 2; j++) {
                int d = 2*lane + 64*j;
                float2 gg = *(const float2*)(g2 + d);
                float2 bb = *(const float2*)(be2 + d);
                float2 o;
                o.x = (v[2*j]   - mean) * inv * gg.x + bb.x;
                o.y = (v[2*j+1] - mean) * inv * gg.y + bb.y;
                *(float2*)(os + row*128 + d) = o;
            }
        }
        __syncthreads();

        // LIF2 + residual: threads tid<128 own d; scan chunk, write out
        if (tid < 128) {
            const float* xp = x   + xbase + (size_t)c * CH * DD + tid;
            float*       op = out + xbase + (size_t)c * CH * DD + tid;
            float v = v2;
            #pragma unroll
            for (int t = 0; t < CH; t++) {
                float hm = v + (os[t*128 + tid] - v) * 0.5f;
                float s  = (hm >= 1.f) ? 1.f : 0.f;
                v = (hm >= 1.f) ? 0.f : hm;
                op[(size_t)t * DD] = xp[(size_t)t * DD] + s;
            }
            v2 = v;
        }
        __syncthreads();   // before next chunk overwrites h1s/ss2
    }
}

// ---------------------------------------------------------------------------
extern "C" void kernel_launch(void* const* d_in, const int* in_sizes, int n_in,
                              void* d_out, int out_size)
{
    const float* x   = (const float*)d_in[0];
    const float* W1  = (const float*)d_in[1];
    const float* b1  = (const float*)d_in[2];
    const float* g1  = (const float*)d_in[3];
    const float* be1 = (const float*)d_in[4];
    const float* W2  = (const float*)d_in[5];
    const float* b2  = (const float*)d_in[6];
    const float* g2  = (const float*)d_in[7];
    const float* be2 = (const float*)d_in[8];
    float* out = (float*)d_out;

    (void)in_sizes; (void)n_in; (void)out_size;

    const size_t g1_smem = G1_SMEM_FLOATS * sizeof(float);   // 196608 B
    const size_t fb_smem = FB_SMEM_FLOATS * sizeof(float);   // 229376 B
    cudaFuncSetAttribute(gemm1_ln_kernel,
                         cudaFuncAttributeMaxDynamicSharedMemorySize, (int)g1_smem);
    cudaFuncSetAttribute(fused2_kernel,
                         cudaFuncAttributeMaxDynamicSharedMemorySize, (int)fb_smem);

    gemm1_ln_kernel<<<NROWS/64, 256, g1_smem>>>(x, W1, b1, g1, be1);
    fused2_kernel<<<BB, 256, fb_smem>>>(x, W2, b2, g2, be2, out);
}

// round 4
// speedup vs baseline: 1.1226x; 1.1226x over previous
#include <cuda_runtime.h>
#include <cstdint>

// Problem dims (fixed by the dataset)
#define BB 256
#define TT 256
#define DD 128
#define HH 256
#define NROWS (BB*TT)          // 65536

// Scratch: h1 (post-LN, pre-LIF1) [B,T,H]
__device__ __align__(16) float g_h1[(size_t)NROWS * HH];   // 67 MB

typedef unsigned long long ull;

// ---------------------------------------------------------------------------
// packed fp32x2 helpers (sm_10x FFMA2 — PTX-only, ptxas never auto-emits)
// ---------------------------------------------------------------------------
__device__ __forceinline__ ull pack2(float lo, float hi) {
    ull p;
    asm("mov.b64 %0, {%1, %2};" : "=l"(p) : "f"(lo), "f"(hi));
    return p;
}
__device__ __forceinline__ void unpack2(ull p, float& lo, float& hi) {
    asm("mov.b64 {%0, %1}, %2;" : "=f"(lo), "=f"(hi) : "l"(p));
}
__device__ __forceinline__ void fma2(ull& acc, ull a, ull b) {
    asm("fma.rn.f32x2 %0, %1, %2, %0;" : "+l"(acc) : "l"(a), "l"(b));
}

// ---------------------------------------------------------------------------
// GEMM1 + bias + LayerNorm(H):  g_h1[row][h] = LN( dot(x[row,:], W1[h,:]) + b1 )
// Block: 64 rows, 256 thr. W1 staged k-major [128][256]; x staged DUPLICATED
// {v,v} pairs, read as ONE broadcast LDS.128 per row per 2k (2 operands, no
// MOVs). Lane owns h 4l..4l+3 and 128+4l..+3 -> W reads are 2 LDS.128/k.
// ---------------------------------------------------------------------------
#define G1_SMEM_FLOATS (128*256 + 64*256)
__global__ __launch_bounds__(256, 1)
void gemm1_ln_kernel(const float* __restrict__ x,
                     const float* __restrict__ W1,
                     const float* __restrict__ b1,
                     const float* __restrict__ g1,
                     const float* __restrict__ be1)
{
    extern __shared__ float sm[];
    float* wst = sm;                 // [k=128][h=256]
    float* xs2 = sm + 128*256;       // [r=64][2k dup = 256]

    const int tid = threadIdx.x;
    const int rowBase = blockIdx.x * 64;

    // Stage W1 transposed: thread tid owns h=tid, streams its gmem row.
    {
        const float4* W4 = (const float4*)W1;       // [h][k4] 256x32
        const int h = tid;
        #pragma unroll
        for (int i = 0; i < 32; i++) {
            float4 v = W4[h*32 + i];
            int k = i*4;
            wst[(k+0)*256 + h] = v.x;
            wst[(k+1)*256 + h] = v.y;
            wst[(k+2)*256 + h] = v.z;
            wst[(k+3)*256 + h] = v.w;
        }
    }
    // Stage x rows duplicated: xs2[r*256 + 2k + {0,1}] = x[r][k]
    {
        const float2* X2 = (const float2*)(x + (size_t)rowBase * DD);  // 4096 float2
        #pragma unroll
        for (int i = 0; i < 16; i++) {
            int s2 = tid + i*256;            // float2 index: r = s2>>6, kp = s2&63
            float2 v = X2[s2];
            int r = s2 >> 6, k = (s2 & 63) * 2;
            *(float2*)(xs2 + r*256 + 2*k)     = make_float2(v.x, v.x);
            *(float2*)(xs2 + r*256 + 2*k + 2) = make_float2(v.y, v.y);
        }
    }
    __syncthreads();

    const int lane = tid & 31;
    const int wrp  = tid >> 5;
    const int rowOff = wrp * 8;

    // acc[jj][r]: jj=0 -> h (4l,4l+1); 1 -> (4l+2,4l+3); 2 -> (128+4l,+1); 3 -> (+2,+3)
    ull acc[4][8];
    #pragma unroll
    for (int hj = 0; hj < 2; hj++)
        #pragma unroll
        for (int pi = 0; pi < 2; pi++) {
            float2 bb = *(const float2*)(b1 + 4*lane + 128*hj + 2*pi);
            ull bp = pack2(bb.x, bb.y);
            #pragma unroll
            for (int r = 0; r < 8; r++) acc[hj*2 + pi][r] = bp;
        }

    #pragma unroll 2
    for (int k = 0; k < 128; k += 2) {
        ulonglong2 wA0 = *(const ulonglong2*)(wst + k*256       + 4*lane);
        ulonglong2 wB0 = *(const ulonglong2*)(wst + k*256 + 128 + 4*lane);
        ulonglong2 wA1 = *(const ulonglong2*)(wst + (k+1)*256       + 4*lane);
        ulonglong2 wB1 = *(const ulonglong2*)(wst + (k+1)*256 + 128 + 4*lane);
        #pragma unroll
        for (int r = 0; r < 8; r++) {
            ulonglong2 xp = *(const ulonglong2*)(xs2 + (rowOff + r)*256 + 2*k);
            fma2(acc[0][r], wA0.x, xp.x);
            fma2(acc[1][r], wA0.y, xp.x);
            fma2(acc[2][r], wB0.x, xp.x);
            fma2(acc[3][r], wB0.y, xp.x);
            fma2(acc[0][r], wA1.x, xp.y);
            fma2(acc[1][r], wA1.y, xp.y);
            fma2(acc[2][r], wB1.x, xp.y);
            fma2(acc[3][r], wB1.y, xp.y);
        }
    }

    // Warp-local LayerNorm per row (256 h over 32 lanes x 8 values)
    #pragma unroll
    for (int r = 0; r < 8; r++) {
        float v[8];
        unpack2(acc[0][r], v[0], v[1]);
        unpack2(acc[1][r], v[2], v[3]);
        unpack2(acc[2][r], v[4], v[5]);
        unpack2(acc[3][r], v[6], v[7]);
        float sum = 0.f, sq = 0.f;
        #pragma unroll
        for (int i = 0; i < 8; i++) { sum += v[i]; sq += v[i]*v[i]; }
        #pragma unroll
        for (int o = 16; o; o >>= 1) {
            sum += __shfl_xor_sync(0xffffffffu, sum, o);
            sq  += __shfl_xor_sync(0xffffffffu, sq,  o);
        }
        float mean = sum * (1.f/256.f);
        float var  = fmaxf(sq * (1.f/256.f) - mean*mean, 0.f) + 1e-5f;
        float inv  = rsqrtf(var);
        inv = inv * (1.5f - 0.5f * var * inv * inv);   // Newton -> fp32-exact rsqrt
        float* op = g_h1 + (size_t)(rowBase + rowOff + r) * HH;
        #pragma unroll
        for (int hj = 0; hj < 2; hj++) {
            int h = 4*lane + 128*hj;
            float4 gg = *(const float4*)(g1 + h);
            float4 bb = *(const float4*)(be1 + h);
            float4 o;
            o.x = (v[4*hj+0] - mean) * inv * gg.x + bb.x;
            o.y = (v[4*hj+1] - mean) * inv * gg.y + bb.y;
            o.z = (v[4*hj+2] - mean) * inv * gg.z + bb.z;
            o.w = (v[4*hj+3] - mean) * inv * gg.w + bb.w;
            *(float4*)(op + h) = o;
        }
    }
}

// ---------------------------------------------------------------------------
// Fused: LIF1 -> GEMM2 -> LN(D) -> LIF2 -> +residual -> out
// Block = TWO batches (512 thr, halves share the W2 smem tile); grid 128 =
// one wave on 148 SMs. Per chunk of CH=32 t:
//   LIF1 (gmem-direct, reg-prefetched) writes TRANSPOSED spikes s_t[k][t]
//   GEMM2 row-paired: acc{r0,r1}[d] += {w_d,w_d} x {s_r0,s_r1}; spike operand
//   is a broadcast ulonglong2, only W needs a register dup (4 MOVs/k).
//   LN(D) warp-local -> os (aliases s_t) -> LIF2 + residual -> out.
// ---------------------------------------------------------------------------
#define FCH 32
#define FNCH (TT/FCH)        // 8
#define STP 36               // s_t row pad: 16B-aligned reads, cf STS.128 stores
#define FB_SMEM_FLOATS (256*128 + 2*256*STP)
__global__ __launch_bounds__(512, 1)
void fused2_kernel(const float* __restrict__ x,
                   const float* __restrict__ W2,
                   const float* __restrict__ b2,
                   const float* __restrict__ g2,
                   const float* __restrict__ be2,
                   float* __restrict__ out)
{
    extern __shared__ float sm[];
    float* wst = sm;                               // [k=h=256][d=128], shared

    const int tid  = threadIdx.x;
    const int half = tid >> 8;                     // 0/1: which batch
    const int htid = tid & 255;                    // h index within batch
    float* s_t = sm + 256*128 + half * (256*STP);  // [k=256][STP] transposed spikes
    float* os  = s_t;                              // alias: [32][132] post-GEMM

    const int b    = blockIdx.x * 2 + half;
    const int lane = tid & 31;
    const int w8   = (tid >> 5) & 7;               // warp within half
    const int dhalf = w8 >> 2;                     // d half: 0 or 1
    const int rg    = w8 & 3;                      // row group: rows rg*8..+7
    const int d0 = dhalf*64 + 2*lane;              // lane owns d0, d0+1

    const float* h1base = g_h1 + (size_t)b * (TT * HH);
    const size_t xbase  = (size_t)b * (TT * DD);

    // Prefetch chunk 0 (thread owns h=htid, 32 t values; coalesced per t)
    float pf[FCH];
    #pragma unroll
    for (int t = 0; t < FCH; t++) pf[t] = h1base[t*HH + htid];

    // Stage W2 k-major: W2 gmem is [d=128][h=256] row-major.
    {
        const float4* W4 = (const float4*)W2;      // [d][h4] 128x64
        const int d = tid & 127, q = tid >> 7;     // q: 0..3, h quarter
        #pragma unroll
        for (int i = 0; i < 16; i++) {
            float4 v = W4[d*64 + q*16 + i];
            int h = (q*16 + i) * 4;
            wst[(h+0)*128 + d] = v.x;
            wst[(h+1)*128 + d] = v.y;
            wst[(h+2)*128 + d] = v.z;
            wst[(h+3)*128 + d] = v.w;
        }
    }

    const ull bd0 = pack2(b2[d0],   b2[d0]);
    const ull bd1 = pack2(b2[d0+1], b2[d0+1]);
    float v1 = 0.f, v2 = 0.f;
    __syncthreads();

    for (int c = 0; c < FNCH; c++) {
        // ---- LIF1: pf -> transposed spikes (STS.128, conflict-free) ----
        {
            float v = v1;
            #pragma unroll
            for (int t4 = 0; t4 < FCH/4; t4++) {
                float4 s4;
                float hm;
                hm = v + (pf[4*t4+0] - v)*0.5f; s4.x = (hm >= 1.f) ? 1.f : 0.f; v = (hm >= 1.f) ? 0.f : hm;
                hm = v + (pf[4*t4+1] - v)*0.5f; s4.y = (hm >= 1.f) ? 1.f : 0.f; v = (hm >= 1.f) ? 0.f : hm;
                hm = v + (pf[4*t4+2] - v)*0.5f; s4.z = (hm >= 1.f) ? 1.f : 0.f; v = (hm >= 1.f) ? 0.f : hm;
                hm = v + (pf[4*t4+3] - v)*0.5f; s4.w = (hm >= 1.f) ? 1.f : 0.f; v = (hm >= 1.f) ? 0.f : hm;
                *(float4*)(s_t + htid*STP + 4*t4) = s4;
            }
            v1 = v;
        }
        __syncthreads();

        // prefetch next chunk (completes during GEMM)
        if (c + 1 < FNCH) {
            const float* hn = h1base + (size_t)(c+1) * FCH * HH;
            #pragma unroll
            for (int t = 0; t < FCH; t++) pf[t] = hn[t*HH + htid];
        }

        // ---- GEMM2: acc[p][j] = rows (rg*8+2j, +1) x d0+p over k=256 ----
        ull acc[2][4];
        #pragma unroll
        for (int j = 0; j < 4; j++) { acc[0][j] = bd0; acc[1][j] = bd1; }

        #pragma unroll 4
        for (int k = 0; k < 256; k++) {
            float2 wv = *(const float2*)(wst + k*128 + d0);
            ull wd0 = pack2(wv.x, wv.x);
            ull wd1 = pack2(wv.y, wv.y);
            ulonglong2 sA = *(const ulonglong2*)(s_t + k*STP + rg*8);
            ulonglong2 sB = *(const ulonglong2*)(s_t + k*STP + rg*8 + 4);
            fma2(acc[0][0], wd0, sA.x); fma2(acc[1][0], wd1, sA.x);
            fma2(acc[0][1], wd0, sA.y); fma2(acc[1][1], wd1, sA.y);
            fma2(acc[0][2], wd0, sB.x); fma2(acc[1][2], wd1, sB.x);
            fma2(acc[0][3], wd0, sB.y); fma2(acc[1][3], wd1, sB.y);
        }
        __syncthreads();   // all reads of s_t done before os (alias) writes

        // ---- store acc -> os[32][132] ----
        #pragma unroll
        for (int j = 0; j < 4; j++) {
            int r0 = rg*8 + 2*j;
            float ve, vo;
            unpack2(acc[0][j], ve, vo);
            os[r0*132 + d0]     = ve;
            os[(r0+1)*132 + d0] = vo;
            unpack2(acc[1][j], ve, vo);
            os[r0*132 + d0 + 1]     = ve;
            os[(r0+1)*132 + d0 + 1] = vo;
        }
        __syncthreads();

        // ---- LayerNorm over D=128 per row (8 warps/half x 4 rows) ----
        #pragma unroll
        for (int rr = 0; rr < 4; rr++) {
            int row = w8*4 + rr;
            float v[4];
            #pragma unroll
            for (int i = 0; i < 4; i++) v[i] = os[row*132 + lane + 32*i];
            float sum = 0.f, sq = 0.f;
            #pragma unroll
            for (int i = 0; i < 4; i++) { sum += v[i]; sq += v[i]*v[i]; }
            #pragma unroll
            for (int o = 16; o; o >>= 1) {
                sum += __shfl_xor_sync(0xffffffffu, sum, o);
                sq  += __shfl_xor_sync(0xffffffffu, sq,  o);
            }
            float mean = sum * (1.f/128.f);
            float var  = fmaxf(sq * (1.f/128.f) - mean*mean, 0.f) + 1e-5f;
            float inv  = rsqrtf(var);
            inv = inv * (1.5f - 0.5f * var * inv * inv);
            #pragma unroll
            for (int i = 0; i < 4; i++) {
                int d = lane + 32*i;
                os[row*132 + d] = (v[i] - mean) * inv * g2[d] + be2[d];
            }
        }
        __syncthreads();

        // ---- LIF2 + residual ----
        if (htid < 128) {
            const float* xp = x   + xbase + (size_t)c * FCH * DD + htid;
            float*       op = out + xbase + (size_t)c * FCH * DD + htid;
            float v = v2;
            #pragma unroll
            for (int t = 0; t < FCH; t++) {
                float hm = v + (os[t*132 + htid] - v) * 0.5f;
                float s  = (hm >= 1.f) ? 1.f : 0.f;
                v = (hm >= 1.f) ? 0.f : hm;
                op[(size_t)t * DD] = xp[(size_t)t * DD] + s;
            }
            v2 = v;
        }
        __syncthreads();   // before next chunk overwrites s_t/os
    }
}

// ---------------------------------------------------------------------------
extern "C" void kernel_launch(void* const* d_in, const int* in_sizes, int n_in,
                              void* d_out, int out_size)
{
    const float* x   = (const float*)d_in[0];
    const float* W1  = (const float*)d_in[1];
    const float* b1  = (const float*)d_in[2];
    const float* g1  = (const float*)d_in[3];
    const float* be1 = (const float*)d_in[4];
    const float* W2  = (const float*)d_in[5];
    const float* b2  = (const float*)d_in[6];
    const float* g2  = (const float*)d_in[7];
    const float* be2 = (const float*)d_in[8];
    float* out = (float*)d_out;

    (void)in_sizes; (void)n_in; (void)out_size;

    const size_t g1_smem = G1_SMEM_FLOATS * sizeof(float);   // 196608 B
    const size_t fb_smem = FB_SMEM_FLOATS * sizeof(float);   // 204800 B
    cudaFuncSetAttribute(gemm1_ln_kernel,
                         cudaFuncAttributeMaxDynamicSharedMemorySize, (int)g1_smem);
    cudaFuncSetAttribute(fused2_kernel,
                         cudaFuncAttributeMaxDynamicSharedMemorySize, (int)fb_smem);

    gemm1_ln_kernel<<<NROWS/64, 256, g1_smem>>>(x, W1, b1, g1, be1);
    fused2_kernel<<<BB/2, 512, fb_smem>>>(x, W2, b2, g2, be2, out);
}

// round 6
// speedup vs baseline: 1.2907x; 1.1497x over previous
#include <cuda_runtime.h>
#include <cuda_bf16.h>
#include <cstdint>

// Problem dims (fixed by the dataset)
#define BB 256
#define TT 256
#define DD 128
#define HH 256
#define NROWS (BB*TT)          // 65536

// Scratch: h1 (post-LN, pre-LIF1) [B,T,H]
__device__ __align__(16) float g_h1[(size_t)NROWS * HH];   // 67 MB

typedef unsigned long long ull;

// ---------------------------------------------------------------------------
// packed fp32x2 helpers (FFMA2) for the fused kernel
// ---------------------------------------------------------------------------
__device__ __forceinline__ ull pack2(float lo, float hi) {
    ull p; asm("mov.b64 %0, {%1, %2};" : "=l"(p) : "f"(lo), "f"(hi)); return p;
}
__device__ __forceinline__ void unpack2(ull p, float& lo, float& hi) {
    asm("mov.b64 {%0, %1}, %2;" : "=f"(lo), "=f"(hi) : "l"(p));
}
__device__ __forceinline__ void fma2(ull& acc, ull a, ull b) {
    asm("fma.rn.f32x2 %0, %1, %2, %0;" : "+l"(acc) : "l"(a), "l"(b));
}

// ---------------------------------------------------------------------------
// mma.sync / ldmatrix helpers (family-portable; NO tcgen05 — harness PTX
// target is plain sm_103, arch-specific features are rejected by ptxas)
// ---------------------------------------------------------------------------
__device__ __forceinline__ uint32_t smem_to_u32(const void* p) {
    uint32_t a;
    asm("{ .reg .u64 t; cvta.to.shared.u64 t, %1; cvt.u32.u64 %0, t; }"
        : "=r"(a) : "l"(p));
    return a;
}
#define LDSM4(r, addr) \
    asm volatile("ldmatrix.sync.aligned.m8n8.x4.shared.b16 {%0,%1,%2,%3}, [%4];" \
        : "=r"((r)[0]), "=r"((r)[1]), "=r"((r)[2]), "=r"((r)[3]) : "r"(addr))
#define MMA16816(D, a, b0, b1) \
    asm volatile("mma.sync.aligned.m16n8k16.row.col.f32.bf16.bf16.f32 " \
        "{%0,%1,%2,%3}, {%4,%5,%6,%7}, {%8,%9}, {%0,%1,%2,%3};" \
        : "+f"((D)[0]), "+f"((D)[1]), "+f"((D)[2]), "+f"((D)[3]) \
        : "r"((a)[0]), "r"((a)[1]), "r"((a)[2]), "r"((a)[3]), "r"(b0), "r"(b1))

__device__ __forceinline__ uint32_t packbf(__nv_bfloat16 a, __nv_bfloat16 b) {
    return (uint32_t)__bfloat16_as_ushort(a) | ((uint32_t)__bfloat16_as_ushort(b) << 16);
}
// split a float2 into 3 packed-bf16 terms: f = h + m + l (+ ~2^-26 residual)
__device__ __forceinline__ void split3(float2 f, uint32_t& h, uint32_t& m, uint32_t& l) {
    __nv_bfloat16 hx = __float2bfloat16(f.x); float rx = f.x - __bfloat162float(hx);
    __nv_bfloat16 mx = __float2bfloat16(rx);  rx -= __bfloat162float(mx);
    __nv_bfloat16 lx = __float2bfloat16(rx);
    __nv_bfloat16 hy = __float2bfloat16(f.y); float ry = f.y - __bfloat162float(hy);
    __nv_bfloat16 my = __float2bfloat16(ry);  ry -= __bfloat162float(my);
    __nv_bfloat16 ly = __float2bfloat16(ry);
    h = packbf(hx, hy); m = packbf(mx, my); l = packbf(lx, ly);
}

// ---------------------------------------------------------------------------
// GEMM1 via mma.sync bf16x3 (6 terms, fp32 acc) + bias + LayerNorm(H)
// Block: 512 thr = 16 warps (4 M-groups x 4 N-groups). Block tile M=128,
// N=256, K=128. W1 split into 3 bf16 planes in smem ([h][k], XOR-swizzled
// 16B units for conflict-free ldmatrix). A fragments built in registers
// straight from gmem (x stays fp32 in L1). 48 mma-steps, D in registers.
// ---------------------------------------------------------------------------
#define WT_BYTES 65536                         // one bf16 W plane [256][128]
#define OFF_RED  (3*256*4)                     // after b1/g1/be1: red[128][8]
#define OFF_STAT (OFF_RED + 128*8*4)           // stat[128][2]
#define OFF_W    8192
#define G1_SMEM_BYTES (OFF_W + 3*WT_BYTES)     // 204800

__global__ __launch_bounds__(512, 1)
void gemm1_mma_kernel(const float* __restrict__ x,
                      const float* __restrict__ W1,
                      const float* __restrict__ b1,
                      const float* __restrict__ g1,
                      const float* __restrict__ be1)
{
    extern __shared__ __align__(16) char smem[];
    float* b1s  = (float*)smem;            // [256]
    float* g1s  = b1s + 256;               // [256]
    float* be1s = g1s + 256;               // [256]
    float* red  = (float*)(smem + OFF_RED);    // [128][8]: 4 wn x (sum,sq)
    float* stat = (float*)(smem + OFF_STAT);   // [128][2]: mean, inv
    char*  wsm  = smem + OFF_W;

    const int tid  = threadIdx.x;
    const int lane = tid & 31;
    const int wid  = tid >> 5;
    const int wm   = wid >> 2;             // M group 0..3 (32 rows each)
    const int wn   = wid & 3;              // N group 0..3 (64 h each)
    const int rowBase = blockIdx.x * 128;

    if (tid < 256) { b1s[tid] = b1[tid]; g1s[tid] = g1[tid]; be1s[tid] = be1[tid]; }

    // ---- Stage W1 -> 3 swizzled bf16 planes ----
    #pragma unroll 4
    for (int i = 0; i < 32; i++) {
        int idx = tid + i*512;             // 16384 (h, kpair) units
        int h = idx >> 6, k = (idx & 63) * 2;
        float2 w = *(const float2*)(W1 + h*128 + k);
        uint32_t ph, pm, pl;
        split3(w, ph, pm, pl);
        uint32_t off = (uint32_t)h*256 + ((((uint32_t)k >> 3) ^ (h & 7)) << 4)
                     + ((k & 7) << 1);
        *(uint32_t*)(wsm + off)              = ph;
        *(uint32_t*)(wsm + WT_BYTES + off)   = pm;
        *(uint32_t*)(wsm + 2*WT_BYTES + off) = pl;
    }
    __syncthreads();

    // ldmatrix lane address components (B = W[h][k] row-major == col-major B)
    const int brow = wn*64 + (lane & 7) + ((lane >> 4) << 3);  // h row
    const int bsel = (lane >> 3) & 1;                          // k half (0/8)
    const uint32_t wsm_u = smem_to_u32(wsm);

    float d[2][8][4];
    #pragma unroll
    for (int mt = 0; mt < 2; mt++)
        #pragma unroll
        for (int nt = 0; nt < 8; nt++)
            #pragma unroll
            for (int i = 0; i < 4; i++) d[mt][nt][i] = 0.f;

    const float* xg = x + (size_t)(rowBase + wm*32) * DD;

    for (int ks = 0; ks < 8; ks++) {
        // ---- A fragments (3 terms) from gmem, in registers ----
        uint32_t ah[2][4], am[2][4], al[2][4];
        #pragma unroll
        for (int mt = 0; mt < 2; mt++) {
            const float* xr = xg + (mt*16 + (lane >> 2))*DD + ks*16 + (lane & 3)*2;
            float2 f0 = *(const float2*)(xr);
            float2 f1 = *(const float2*)(xr + 8*DD);
            float2 f2 = *(const float2*)(xr + 8);
            float2 f3 = *(const float2*)(xr + 8*DD + 8);
            split3(f0, ah[mt][0], am[mt][0], al[mt][0]);
            split3(f1, ah[mt][1], am[mt][1], al[mt][1]);
            split3(f2, ah[mt][2], am[mt][2], al[mt][2]);
            split3(f3, ah[mt][3], am[mt][3], al[mt][3]);
        }
        // ---- B fragments + 6-term MMAs over 4 n-pairs ----
        #pragma unroll
        for (int np = 0; np < 4; np++) {
            int row = brow + np*16;
            uint32_t boff = (uint32_t)row*256 + ((((ks << 1) | bsel) ^ (row & 7)) << 4);
            uint32_t bh[4], bm[4], bl[4];
            LDSM4(bh, wsm_u + boff);
            LDSM4(bm, wsm_u + WT_BYTES + boff);
            LDSM4(bl, wsm_u + 2*WT_BYTES + boff);
            #pragma unroll
            for (int mt = 0; mt < 2; mt++)
                #pragma unroll
                for (int ns = 0; ns < 2; ns++) {
                    float* D = d[mt][np*2 + ns];
                    MMA16816(D, ah[mt], bh[ns*2], bh[ns*2+1]);   // hh
                    MMA16816(D, ah[mt], bm[ns*2], bm[ns*2+1]);   // hm
                    MMA16816(D, am[mt], bh[ns*2], bh[ns*2+1]);   // mh
                    MMA16816(D, am[mt], bm[ns*2], bm[ns*2+1]);   // mm
                    MMA16816(D, ah[mt], bl[ns*2], bl[ns*2+1]);   // hl
                    MMA16816(D, al[mt], bh[ns*2], bh[ns*2+1]);   // lh
                }
        }
    }

    // ---- bias + per-lane partial sums (rows l/4+{0,8} per mtile) ----
    float psum[2][2] = {{0.f,0.f},{0.f,0.f}}, psq[2][2] = {{0.f,0.f},{0.f,0.f}};
    #pragma unroll
    for (int mt = 0; mt < 2; mt++)
        #pragma unroll
        for (int nt = 0; nt < 8; nt++) {
            int col = wn*64 + nt*8 + (lane & 3)*2;
            float bx = b1s[col], by = b1s[col+1];
            float* D = d[mt][nt];
            D[0] += bx; D[1] += by; D[2] += bx; D[3] += by;
            psum[mt][0] += D[0] + D[1]; psq[mt][0] += D[0]*D[0] + D[1]*D[1];
            psum[mt][1] += D[2] + D[3]; psq[mt][1] += D[2]*D[2] + D[3]*D[3];
        }
    #pragma unroll
    for (int mt = 0; mt < 2; mt++)
        #pragma unroll
        for (int rh = 0; rh < 2; rh++) {
            #pragma unroll
            for (int o = 1; o <= 2; o <<= 1) {
                psum[mt][rh] += __shfl_xor_sync(0xffffffffu, psum[mt][rh], o);
                psq[mt][rh]  += __shfl_xor_sync(0xffffffffu, psq[mt][rh],  o);
            }
            if ((lane & 3) == 0) {
                int r = wm*32 + mt*16 + rh*8 + (lane >> 2);
                red[r*8 + wn*2 + 0] = psum[mt][rh];
                red[r*8 + wn*2 + 1] = psq[mt][rh];
            }
        }
    __syncthreads();
    if (tid < 128) {
        float s = red[tid*8+0] + red[tid*8+2] + red[tid*8+4] + red[tid*8+6];
        float q = red[tid*8+1] + red[tid*8+3] + red[tid*8+5] + red[tid*8+7];
        float mean = s * (1.f/256.f);
        float var  = fmaxf(q * (1.f/256.f) - mean*mean, 0.f) + 1e-5f;
        float inv  = rsqrtf(var);
        inv = inv * (1.5f - 0.5f * var * inv * inv);   // fp32-exact rsqrt
        stat[tid*2]   = mean;
        stat[tid*2+1] = inv;
    }
    __syncthreads();

    // ---- normalize + write ----
    #pragma unroll
    for (int mt = 0; mt < 2; mt++) {
        int r0 = wm*32 + mt*16 + (lane >> 2);
        float mean0 = stat[r0*2],     inv0 = stat[r0*2+1];
        float mean1 = stat[(r0+8)*2], inv1 = stat[(r0+8)*2+1];
        float* o0 = g_h1 + (size_t)(rowBase + r0) * HH;
        float* o1 = o0 + 8*HH;
        #pragma unroll
        for (int nt = 0; nt < 8; nt++) {
            int col = wn*64 + nt*8 + (lane & 3)*2;
            float gx = g1s[col], gy = g1s[col+1];
            float ex = be1s[col], ey = be1s[col+1];
            float* D = d[mt][nt];
            float2 w0, w1;
            w0.x = (D[0] - mean0) * inv0 * gx + ex;
            w0.y = (D[1] - mean0) * inv0 * gy + ey;
            w1.x = (D[2] - mean1) * inv1 * gx + ex;
            w1.y = (D[3] - mean1) * inv1 * gy + ey;
            *(float2*)(o0 + col) = w0;
            *(float2*)(o1 + col) = w1;
        }
    }
}

// ---------------------------------------------------------------------------
// Fused: LIF1 -> GEMM2 -> LN(D) -> LIF2 -> +residual -> out   (unchanged R4)
// ---------------------------------------------------------------------------
#define FCH 32
#define FNCH (TT/FCH)        // 8
#define STP 36
#define FB_SMEM_FLOATS (256*128 + 2*256*STP)
__global__ __launch_bounds__(512, 1)
void fused2_kernel(const float* __restrict__ x,
                   const float* __restrict__ W2,
                   const float* __restrict__ b2,
                   const float* __restrict__ g2,
                   const float* __restrict__ be2,
                   float* __restrict__ out)
{
    extern __shared__ float sm[];
    float* wst = sm;                               // [k=h=256][d=128], shared

    const int tid  = threadIdx.x;
    const int half = tid >> 8;
    const int htid = tid & 255;
    float* s_t = sm + 256*128 + half * (256*STP);  // [k=256][STP] transposed spikes
    float* os  = s_t;

    const int b    = blockIdx.x * 2 + half;
    const int lane = tid & 31;
    const int w8   = (tid >> 5) & 7;
    const int dhalf = w8 >> 2;
    const int rg    = w8 & 3;
    const int d0 = dhalf*64 + 2*lane;

    const float* h1base = g_h1 + (size_t)b * (TT * HH);
    const size_t xbase  = (size_t)b * (TT * DD);

    float pf[FCH];
    #pragma unroll
    for (int t = 0; t < FCH; t++) pf[t] = h1base[t*HH + htid];

    {
        const float4* W4 = (const float4*)W2;
        const int d = tid & 127, q = tid >> 7;
        #pragma unroll
        for (int i = 0; i < 16; i++) {
            float4 v = W4[d*64 + q*16 + i];
            int h = (q*16 + i) * 4;
            wst[(h+0)*128 + d] = v.x;
            wst[(h+1)*128 + d] = v.y;
            wst[(h+2)*128 + d] = v.z;
            wst[(h+3)*128 + d] = v.w;
        }
    }

    const ull bd0 = pack2(b2[d0],   b2[d0]);
    const ull bd1 = pack2(b2[d0+1], b2[d0+1]);
    float v1 = 0.f, v2 = 0.f;
    __syncthreads();

    for (int c = 0; c < FNCH; c++) {
        {
            float v = v1;
            #pragma unroll
            for (int t4 = 0; t4 < FCH/4; t4++) {
                float4 s4;
                float hm;
                hm = v + (pf[4*t4+0] - v)*0.5f; s4.x = (hm >= 1.f) ? 1.f : 0.f; v = (hm >= 1.f) ? 0.f : hm;
                hm = v + (pf[4*t4+1] - v)*0.5f; s4.y = (hm >= 1.f) ? 1.f : 0.f; v = (hm >= 1.f) ? 0.f : hm;
                hm = v + (pf[4*t4+2] - v)*0.5f; s4.z = (hm >= 1.f) ? 1.f : 0.f; v = (hm >= 1.f) ? 0.f : hm;
                hm = v + (pf[4*t4+3] - v)*0.5f; s4.w = (hm >= 1.f) ? 1.f : 0.f; v = (hm >= 1.f) ? 0.f : hm;
                *(float4*)(s_t + htid*STP + 4*t4) = s4;
            }
            v1 = v;
        }
        __syncthreads();

        if (c + 1 < FNCH) {
            const float* hn = h1base + (size_t)(c+1) * FCH * HH;
            #pragma unroll
            for (int t = 0; t < FCH; t++) pf[t] = hn[t*HH + htid];
        }

        ull acc[2][4];
        #pragma unroll
        for (int j = 0; j < 4; j++) { acc[0][j] = bd0; acc[1][j] = bd1; }

        #pragma unroll 4
        for (int k = 0; k < 256; k++) {
            float2 wv = *(const float2*)(wst + k*128 + d0);
            ull wd0 = pack2(wv.x, wv.x);
            ull wd1 = pack2(wv.y, wv.y);
            ulonglong2 sA = *(const ulonglong2*)(s_t + k*STP + rg*8);
            ulonglong2 sB = *(const ulonglong2*)(s_t + k*STP + rg*8 + 4);
            fma2(acc[0][0], wd0, sA.x); fma2(acc[1][0], wd1, sA.x);
            fma2(acc[0][1], wd0, sA.y); fma2(acc[1][1], wd1, sA.y);
            fma2(acc[0][2], wd0, sB.x); fma2(acc[1][2], wd1, sB.x);
            fma2(acc[0][3], wd0, sB.y); fma2(acc[1][3], wd1, sB.y);
        }
        __syncthreads();

        #pragma unroll
        for (int j = 0; j < 4; j++) {
            int r0 = rg*8 + 2*j;
            float ve, vo;
            unpack2(acc[0][j], ve, vo);
            os[r0*132 + d0]     = ve;
            os[(r0+1)*132 + d0] = vo;
            unpack2(acc[1][j], ve, vo);
            os[r0*132 + d0 + 1]     = ve;
            os[(r0+1)*132 + d0 + 1] = vo;
        }
        __syncthreads();

        #pragma unroll
        for (int rr = 0; rr < 4; rr++) {
            int row = w8*4 + rr;
            float v[4];
            #pragma unroll
            for (int i = 0; i < 4; i++) v[i] = os[row*132 + lane + 32*i];
            float sum = 0.f, sq = 0.f;
            #pragma unroll
            for (int i = 0; i < 4; i++) { sum += v[i]; sq += v[i]*v[i]; }
            #pragma unroll
            for (int o = 16; o; o >>= 1) {
                sum += __shfl_xor_sync(0xffffffffu, sum, o);
                sq  += __shfl_xor_sync(0xffffffffu, sq,  o);
            }
            float mean = sum * (1.f/128.f);
            float var  = fmaxf(sq * (1.f/128.f) - mean*mean, 0.f) + 1e-5f;
            float inv  = rsqrtf(var);
            inv = inv * (1.5f - 0.5f * var * inv * inv);
            #pragma unroll
            for (int i = 0; i < 4; i++) {
                int d = lane + 32*i;
                os[row*132 + d] = (v[i] - mean) * inv * g2[d] + be2[d];
            }
        }
        __syncthreads();

        if (htid < 128) {
            const float* xp = x   + xbase + (size_t)c * FCH * DD + htid;
            float*       op = out + xbase + (size_t)c * FCH * DD + htid;
            float v = v2;
            #pragma unroll
            for (int t = 0; t < FCH; t++) {
                float hm = v + (os[t*132 + htid] - v) * 0.5f;
                float s  = (hm >= 1.f) ? 1.f : 0.f;
                v = (hm >= 1.f) ? 0.f : hm;
                op[(size_t)t * DD] = xp[(size_t)t * DD] + s;
            }
            v2 = v;
        }
        __syncthreads();
    }
}

// ---------------------------------------------------------------------------
extern "C" void kernel_launch(void* const* d_in, const int* in_sizes, int n_in,
                              void* d_out, int out_size)
{
    const float* x   = (const float*)d_in[0];
    const float* W1  = (const float*)d_in[1];
    const float* b1  = (const float*)d_in[2];
    const float* g1  = (const float*)d_in[3];
    const float* be1 = (const float*)d_in[4];
    const float* W2  = (const float*)d_in[5];
    const float* b2  = (const float*)d_in[6];
    const float* g2  = (const float*)d_in[7];
    const float* be2 = (const float*)d_in[8];
    float* out = (float*)d_out;

    (void)in_sizes; (void)n_in; (void)out_size;

    const size_t g1_smem = G1_SMEM_BYTES;                    // 204800 B
    const size_t fb_smem = FB_SMEM_FLOATS * sizeof(float);   // 204800 B
    cudaFuncSetAttribute(gemm1_mma_kernel,
                         cudaFuncAttributeMaxDynamicSharedMemorySize, (int)g1_smem);
    cudaFuncSetAttribute(fused2_kernel,
                         cudaFuncAttributeMaxDynamicSharedMemorySize, (int)fb_smem);

    gemm1_mma_kernel<<<NROWS/128, 512, g1_smem>>>(x, W1, b1, g1, be1);
    fused2_kernel<<<BB/2, 512, fb_smem>>>(x, W2, b2, g2, be2, out);
}

// round 7
// speedup vs baseline: 1.8462x; 1.4304x over previous
#include <cuda_runtime.h>
#include <cuda_bf16.h>
#include <cstdint>

// Problem dims (fixed by the dataset)
#define BB 256
#define TT 256
#define DD 128
#define HH 256
#define NROWS (BB*TT)          // 65536

// Scratch: h1 (post-LN, pre-LIF1) [B,T,H]
__device__ __align__(16) float g_h1[(size_t)NROWS * HH];   // 67 MB

// ---------------------------------------------------------------------------
// mma.sync / ldmatrix helpers (family-portable; NO tcgen05 — harness PTX
// target is plain sm_103, arch-specific features are rejected by ptxas)
// ---------------------------------------------------------------------------
__device__ __forceinline__ uint32_t smem_to_u32(const void* p) {
    uint32_t a;
    asm("{ .reg .u64 t; cvta.to.shared.u64 t, %1; cvt.u32.u64 %0, t; }"
        : "=r"(a) : "l"(p));
    return a;
}
#define LDSM4(r, addr) \
    asm volatile("ldmatrix.sync.aligned.m8n8.x4.shared.b16 {%0,%1,%2,%3}, [%4];" \
        : "=r"((r)[0]), "=r"((r)[1]), "=r"((r)[2]), "=r"((r)[3]) : "r"(addr))
#define MMA16816(D, a, b0, b1) \
    asm volatile("mma.sync.aligned.m16n8k16.row.col.f32.bf16.bf16.f32 " \
        "{%0,%1,%2,%3}, {%4,%5,%6,%7}, {%8,%9}, {%0,%1,%2,%3};" \
        : "+f"((D)[0]), "+f"((D)[1]), "+f"((D)[2]), "+f"((D)[3]) \
        : "r"((a)[0]), "r"((a)[1]), "r"((a)[2]), "r"((a)[3]), "r"(b0), "r"(b1))

__device__ __forceinline__ uint32_t packbf(__nv_bfloat16 a, __nv_bfloat16 b) {
    return (uint32_t)__bfloat16_as_ushort(a) | ((uint32_t)__bfloat16_as_ushort(b) << 16);
}
// split a float2 into 3 packed-bf16 terms: f = h + m + l (+ ~2^-26 residual)
__device__ __forceinline__ void split3(float2 f, uint32_t& h, uint32_t& m, uint32_t& l) {
    __nv_bfloat16 hx = __float2bfloat16(f.x); float rx = f.x - __bfloat162float(hx);
    __nv_bfloat16 mx = __float2bfloat16(rx);  rx -= __bfloat162float(mx);
    __nv_bfloat16 lx = __float2bfloat16(rx);
    __nv_bfloat16 hy = __float2bfloat16(f.y); float ry = f.y - __bfloat162float(hy);
    __nv_bfloat16 my = __float2bfloat16(ry);  ry -= __bfloat162float(my);
    __nv_bfloat16 ly = __float2bfloat16(ry);
    h = packbf(hx, hy); m = packbf(mx, my); l = packbf(lx, ly);
}

// ---------------------------------------------------------------------------
// GEMM1 via mma.sync bf16x3 (6 terms, fp32 acc) + bias + LayerNorm(H)
// (unchanged from R6 — passed with rel_err 0.0)
// ---------------------------------------------------------------------------
#define WT_BYTES 65536                         // one bf16 W plane [256][128]
#define OFF_RED  (3*256*4)
#define OFF_STAT (OFF_RED + 128*8*4)
#define OFF_W    8192
#define G1_SMEM_BYTES (OFF_W + 3*WT_BYTES)     // 204800

__global__ __launch_bounds__(512, 1)
void gemm1_mma_kernel(const float* __restrict__ x,
                      const float* __restrict__ W1,
                      const float* __restrict__ b1,
                      const float* __restrict__ g1,
                      const float* __restrict__ be1)
{
    extern __shared__ __align__(16) char smem[];
    float* b1s  = (float*)smem;
    float* g1s  = b1s + 256;
    float* be1s = g1s + 256;
    float* red  = (float*)(smem + OFF_RED);
    float* stat = (float*)(smem + OFF_STAT);
    char*  wsm  = smem + OFF_W;

    const int tid  = threadIdx.x;
    const int lane = tid & 31;
    const int wid  = tid >> 5;
    const int wm   = wid >> 2;
    const int wn   = wid & 3;
    const int rowBase = blockIdx.x * 128;

    if (tid < 256) { b1s[tid] = b1[tid]; g1s[tid] = g1[tid]; be1s[tid] = be1[tid]; }

    #pragma unroll 4
    for (int i = 0; i < 32; i++) {
        int idx = tid + i*512;
        int h = idx >> 6, k = (idx & 63) * 2;
        float2 w = *(const float2*)(W1 + h*128 + k);
        uint32_t ph, pm, pl;
        split3(w, ph, pm, pl);
        uint32_t off = (uint32_t)h*256 + ((((uint32_t)k >> 3) ^ (h & 7)) << 4)
                     + ((k & 7) << 1);
        *(uint32_t*)(wsm + off)              = ph;
        *(uint32_t*)(wsm + WT_BYTES + off)   = pm;
        *(uint32_t*)(wsm + 2*WT_BYTES + off) = pl;
    }
    __syncthreads();

    const int brow = wn*64 + (lane & 7) + ((lane >> 4) << 3);
    const int bsel = (lane >> 3) & 1;
    const uint32_t wsm_u = smem_to_u32(wsm);

    float d[2][8][4];
    #pragma unroll
    for (int mt = 0; mt < 2; mt++)
        #pragma unroll
        for (int nt = 0; nt < 8; nt++)
            #pragma unroll
            for (int i = 0; i < 4; i++) d[mt][nt][i] = 0.f;

    const float* xg = x + (size_t)(rowBase + wm*32) * DD;

    for (int ks = 0; ks < 8; ks++) {
        uint32_t ah[2][4], am[2][4], al[2][4];
        #pragma unroll
        for (int mt = 0; mt < 2; mt++) {
            const float* xr = xg + (mt*16 + (lane >> 2))*DD + ks*16 + (lane & 3)*2;
            float2 f0 = *(const float2*)(xr);
            float2 f1 = *(const float2*)(xr + 8*DD);
            float2 f2 = *(const float2*)(xr + 8);
            float2 f3 = *(const float2*)(xr + 8*DD + 8);
            split3(f0, ah[mt][0], am[mt][0], al[mt][0]);
            split3(f1, ah[mt][1], am[mt][1], al[mt][1]);
            split3(f2, ah[mt][2], am[mt][2], al[mt][2]);
            split3(f3, ah[mt][3], am[mt][3], al[mt][3]);
        }
        #pragma unroll
        for (int np = 0; np < 4; np++) {
            int row = brow + np*16;
            uint32_t boff = (uint32_t)row*256 + ((((ks << 1) | bsel) ^ (row & 7)) << 4);
            uint32_t bh[4], bm[4], bl[4];
            LDSM4(bh, wsm_u + boff);
            LDSM4(bm, wsm_u + WT_BYTES + boff);
            LDSM4(bl, wsm_u + 2*WT_BYTES + boff);
            #pragma unroll
            for (int mt = 0; mt < 2; mt++)
                #pragma unroll
                for (int ns = 0; ns < 2; ns++) {
                    float* D = d[mt][np*2 + ns];
                    MMA16816(D, ah[mt], bh[ns*2], bh[ns*2+1]);
                    MMA16816(D, ah[mt], bm[ns*2], bm[ns*2+1]);
                    MMA16816(D, am[mt], bh[ns*2], bh[ns*2+1]);
                    MMA16816(D, am[mt], bm[ns*2], bm[ns*2+1]);
                    MMA16816(D, ah[mt], bl[ns*2], bl[ns*2+1]);
                    MMA16816(D, al[mt], bh[ns*2], bh[ns*2+1]);
                }
        }
    }

    float psum[2][2] = {{0.f,0.f},{0.f,0.f}}, psq[2][2] = {{0.f,0.f},{0.f,0.f}};
    #pragma unroll
    for (int mt = 0; mt < 2; mt++)
        #pragma unroll
        for (int nt = 0; nt < 8; nt++) {
            int col = wn*64 + nt*8 + (lane & 3)*2;
            float bx = b1s[col], by = b1s[col+1];
            float* D = d[mt][nt];
            D[0] += bx; D[1] += by; D[2] += bx; D[3] += by;
            psum[mt][0] += D[0] + D[1]; psq[mt][0] += D[0]*D[0] + D[1]*D[1];
            psum[mt][1] += D[2] + D[3]; psq[mt][1] += D[2]*D[2] + D[3]*D[3];
        }
    #pragma unroll
    for (int mt = 0; mt < 2; mt++)
        #pragma unroll
        for (int rh = 0; rh < 2; rh++) {
            #pragma unroll
            for (int o = 1; o <= 2; o <<= 1) {
                psum[mt][rh] += __shfl_xor_sync(0xffffffffu, psum[mt][rh], o);
                psq[mt][rh]  += __shfl_xor_sync(0xffffffffu, psq[mt][rh],  o);
            }
            if ((lane & 3) == 0) {
                int r = wm*32 + mt*16 + rh*8 + (lane >> 2);
                red[r*8 + wn*2 + 0] = psum[mt][rh];
                red[r*8 + wn*2 + 1] = psq[mt][rh];
            }
        }
    __syncthreads();
    if (tid < 128) {
        float s = red[tid*8+0] + red[tid*8+2] + red[tid*8+4] + red[tid*8+6];
        float q = red[tid*8+1] + red[tid*8+3] + red[tid*8+5] + red[tid*8+7];
        float mean = s * (1.f/256.f);
        float var  = fmaxf(q * (1.f/256.f) - mean*mean, 0.f) + 1e-5f;
        float inv  = rsqrtf(var);
        inv = inv * (1.5f - 0.5f * var * inv * inv);
        stat[tid*2]   = mean;
        stat[tid*2+1] = inv;
    }
    __syncthreads();

    #pragma unroll
    for (int mt = 0; mt < 2; mt++) {
        int r0 = wm*32 + mt*16 + (lane >> 2);
        float mean0 = stat[r0*2],     inv0 = stat[r0*2+1];
        float mean1 = stat[(r0+8)*2], inv1 = stat[(r0+8)*2+1];
        float* o0 = g_h1 + (size_t)(rowBase + r0) * HH;
        float* o1 = o0 + 8*HH;
        #pragma unroll
        for (int nt = 0; nt < 8; nt++) {
            int col = wn*64 + nt*8 + (lane & 3)*2;
            float gx = g1s[col], gy = g1s[col+1];
            float ex = be1s[col], ey = be1s[col+1];
            float* D = d[mt][nt];
            float2 w0, w1;
            w0.x = (D[0] - mean0) * inv0 * gx + ex;
            w0.y = (D[1] - mean0) * inv0 * gy + ey;
            w1.x = (D[2] - mean1) * inv1 * gx + ex;
            w1.y = (D[3] - mean1) * inv1 * gy + ey;
            *(float2*)(o0 + col) = w0;
            *(float2*)(o1 + col) = w1;
        }
    }
}

// ---------------------------------------------------------------------------
// Fused: LIF1 -> GEMM2(mma bf16, W2 3-plane split, spikes EXACT bf16)
//        -> LN(D) -> LIF2 -> +residual -> out
// Block = 2 batches (512 thr). Per chunk CH=32 t: LIF1 writes bf16 spikes
// (constant 0x3F80/0, no cvt) into padded tile (528B rows, conflict-free
// ldmatrix); GEMM2 = 3 HMMA terms (W2 split only); LN + LIF2 as before.
// ---------------------------------------------------------------------------
#define W2P_BYTES 65536                       // one bf16 W2 plane [128][512B]
#define SBF_BYTES 16896                       // 32 rows x 528 B
#define OFF_SBF   (3*W2P_BYTES)               // 196608
#define OFF_PAR   (OFF_SBF + 2*SBF_BYTES)     // 230400
#define F2_SMEM_BYTES (OFF_PAR + 3*128*4)     // 231936

__global__ __launch_bounds__(512, 1)
void fused2_mma_kernel(const float* __restrict__ x,
                       const float* __restrict__ W2,
                       const float* __restrict__ b2,
                       const float* __restrict__ g2,
                       const float* __restrict__ be2,
                       float* __restrict__ out)
{
    extern __shared__ __align__(16) char smem[];
    char*  wsm  = smem;                                  // 3 W2 planes
    float* b2s  = (float*)(smem + OFF_PAR);              // [128]
    float* g2s  = b2s + 128;
    float* be2s = g2s + 128;

    const int tid  = threadIdx.x;
    const int half = tid >> 8;
    const int htid = tid & 255;
    const int lane = tid & 31;
    const int w8   = (tid >> 5) & 7;                     // warp within half

    char*  sbf = smem + OFF_SBF + half * SBF_BYTES;      // [32 t][528 B] bf16
    float* os  = (float*)sbf;                            // alias: [32][128] f32

    const int b = blockIdx.x * 2 + half;
    const float* h1base = g_h1 + (size_t)b * (TT * HH);
    const size_t xbase  = (size_t)b * (TT * DD);

    if (tid < 128) { b2s[tid] = b2[tid]; g2s[tid] = g2[tid]; be2s[tid] = be2[tid]; }

    // prefetch chunk 0 of h1
    float pf[32];
    #pragma unroll
    for (int t = 0; t < 32; t++) pf[t] = h1base[t*HH + htid];

    // ---- Stage W2 -> 3 swizzled bf16 planes ([d=128 rows][256 k], 512B rows) ----
    #pragma unroll 4
    for (int i = 0; i < 32; i++) {
        int idx = tid + i*512;                  // 16384 (d, kpair) units
        int dd = idx >> 7, k = (idx & 127) * 2;
        float2 w = *(const float2*)(W2 + dd*256 + k);
        uint32_t ph, pm, pl;
        split3(w, ph, pm, pl);
        uint32_t off = (uint32_t)dd*512 + ((((uint32_t)k >> 3) ^ (dd & 7)) << 4)
                     + ((k & 7) << 1);
        *(uint32_t*)(wsm + off)               = ph;
        *(uint32_t*)(wsm + W2P_BYTES + off)   = pm;
        *(uint32_t*)(wsm + 2*W2P_BYTES + off) = pl;
    }
    __syncthreads();

    // warp tiling within a half: wm2 = m tile (16 t), wn2 = 32-d group
    const int wm2 = w8 & 1;
    const int wn2 = w8 >> 1;
    const uint32_t wsm_u = smem_to_u32(wsm);
    const uint32_t sbf_u = smem_to_u32(sbf);
    const uint32_t a_addr = sbf_u + (uint32_t)(wm2*16 + (lane & 15))*528
                          + ((lane >> 4) << 4);
    const int brow0 = wn2*32 + (lane & 7) + ((lane >> 4) << 3);
    const int bsel  = (lane >> 3) & 1;

    float v1 = 0.f, v2 = 0.f;

    for (int c = 0; c < 8; c++) {
        // ---- LIF1: spikes as constant bf16 bits ----
        {
            float v = v1;
            #pragma unroll
            for (int t = 0; t < 32; t++) {
                float hm = v + (pf[t] - v) * 0.5f;
                *(uint16_t*)(sbf + t*528 + htid*2) = (hm >= 1.f) ? 0x3F80u : 0u;
                v = (hm >= 1.f) ? 0.f : hm;
            }
            v1 = v;
        }
        __syncthreads();

        // prefetch next chunk (hidden behind GEMM)
        if (c + 1 < 8) {
            const float* hn = h1base + (size_t)(c+1) * 32 * HH;
            #pragma unroll
            for (int t = 0; t < 32; t++) pf[t] = hn[t*HH + htid];
        }

        // ---- GEMM2: M=16 t x N=32 d per warp, K=256, 3 W-planes ----
        float D[4][4];
        #pragma unroll
        for (int nt = 0; nt < 4; nt++) {
            int col = wn2*32 + nt*8 + (lane & 3)*2;
            D[nt][0] = b2s[col]; D[nt][1] = b2s[col+1];
            D[nt][2] = b2s[col]; D[nt][3] = b2s[col+1];
        }
        for (int ks = 0; ks < 16; ks++) {
            uint32_t a[4];
            LDSM4(a, a_addr + ks*32);
            #pragma unroll
            for (int p = 0; p < 3; p++) {
                uint32_t bA[4], bB[4];
                {
                    int row = brow0;
                    uint32_t boff = (uint32_t)row*512 +
                                    ((((ks << 1) | bsel) ^ (row & 7)) << 4);
                    LDSM4(bA, wsm_u + p*W2P_BYTES + boff);
                }
                {
                    int row = brow0 + 16;
                    uint32_t boff = (uint32_t)row*512 +
                                    ((((ks << 1) | bsel) ^ (row & 7)) << 4);
                    LDSM4(bB, wsm_u + p*W2P_BYTES + boff);
                }
                MMA16816(D[0], a, bA[0], bA[1]);
                MMA16816(D[1], a, bA[2], bA[3]);
                MMA16816(D[2], a, bB[0], bB[1]);
                MMA16816(D[3], a, bB[2], bB[3]);
            }
        }
        __syncthreads();   // all reads of sbf done before os (alias) writes

        // ---- write D -> os[32][128] ----
        {
            int r0 = wm2*16 + (lane >> 2);
            #pragma unroll
            for (int nt = 0; nt < 4; nt++) {
                int col = wn2*32 + nt*8 + (lane & 3)*2;
                *(float2*)(os + r0*128 + col)     = make_float2(D[nt][0], D[nt][1]);
                *(float2*)(os + (r0+8)*128 + col) = make_float2(D[nt][2], D[nt][3]);
            }
        }
        __syncthreads();

        // ---- LayerNorm over D=128 per row (8 warps x 4 rows) ----
        #pragma unroll
        for (int rr = 0; rr < 4; rr++) {
            int row = w8*4 + rr;
            float v[4];
            #pragma unroll
            for (int i = 0; i < 4; i++) v[i] = os[row*128 + lane + 32*i];
            float sum = 0.f, sq = 0.f;
            #pragma unroll
            for (int i = 0; i < 4; i++) { sum += v[i]; sq += v[i]*v[i]; }
            #pragma unroll
            for (int o = 16; o; o >>= 1) {
                sum += __shfl_xor_sync(0xffffffffu, sum, o);
                sq  += __shfl_xor_sync(0xffffffffu, sq,  o);
            }
            float mean = sum * (1.f/128.f);
            float var  = fmaxf(sq * (1.f/128.f) - mean*mean, 0.f) + 1e-5f;
            float inv  = rsqrtf(var);
            inv = inv * (1.5f - 0.5f * var * inv * inv);
            #pragma unroll
            for (int i = 0; i < 4; i++) {
                int dd = lane + 32*i;
                os[row*128 + dd] = (v[i] - mean) * inv * g2s[dd] + be2s[dd];
            }
        }
        __syncthreads();

        // ---- LIF2 + residual ----
        if (htid < 128) {
            const float* xp = x   + xbase + (size_t)c * 32 * DD + htid;
            float*       op = out + xbase + (size_t)c * 32 * DD + htid;
            float v = v2;
            #pragma unroll
            for (int t = 0; t < 32; t++) {
                float hm = v + (os[t*128 + htid] - v) * 0.5f;
                float s  = (hm >= 1.f) ? 1.f : 0.f;
                v = (hm >= 1.f) ? 0.f : hm;
                op[(size_t)t * DD] = xp[(size_t)t * DD] + s;
            }
            v2 = v;
        }
        __syncthreads();   // before next chunk overwrites sbf/os
    }
}

// ---------------------------------------------------------------------------
extern "C" void kernel_launch(void* const* d_in, const int* in_sizes, int n_in,
                              void* d_out, int out_size)
{
    const float* x   = (const float*)d_in[0];
    const float* W1  = (const float*)d_in[1];
    const float* b1  = (const float*)d_in[2];
    const float* g1  = (const float*)d_in[3];
    const float* be1 = (const float*)d_in[4];
    const float* W2  = (const float*)d_in[5];
    const float* b2  = (const float*)d_in[6];
    const float* g2  = (const float*)d_in[7];
    const float* be2 = (const float*)d_in[8];
    float* out = (float*)d_out;

    (void)in_sizes; (void)n_in; (void)out_size;

    cudaFuncSetAttribute(gemm1_mma_kernel,
                         cudaFuncAttributeMaxDynamicSharedMemorySize, G1_SMEM_BYTES);
    cudaFuncSetAttribute(fused2_mma_kernel,
                         cudaFuncAttributeMaxDynamicSharedMemorySize, F2_SMEM_BYTES);

    gemm1_mma_kernel<<<NROWS/128, 512, G1_SMEM_BYTES>>>(x, W1, b1, g1, be1);
    fused2_mma_kernel<<<BB/2, 512, F2_SMEM_BYTES>>>(x, W2, b2, g2, be2, out);
}

// round 8
// speedup vs baseline: 2.1258x; 1.1515x over previous
#include <cuda_runtime.h>
#include <cuda_bf16.h>
#include <cstdint>

// Problem dims (fixed by the dataset)
#define BB 256
#define TT 256
#define DD 128
#define HH 256
#define NROWS (BB*TT)          // 65536

// Scratch: h1 (post-LN, pre-LIF1) [B,T,H]
__device__ __align__(16) float g_h1[(size_t)NROWS * HH];   // 67 MB

// ---------------------------------------------------------------------------
// mma.sync / ldmatrix helpers (family-portable; NO tcgen05 — harness PTX
// target is plain sm_103, arch-specific features are rejected by ptxas)
// ---------------------------------------------------------------------------
__device__ __forceinline__ uint32_t smem_to_u32(const void* p) {
    uint32_t a;
    asm("{ .reg .u64 t; cvta.to.shared.u64 t, %1; cvt.u32.u64 %0, t; }"
        : "=r"(a) : "l"(p));
    return a;
}
#define LDSM4(r, addr) \
    asm volatile("ldmatrix.sync.aligned.m8n8.x4.shared.b16 {%0,%1,%2,%3}, [%4];" \
        : "=r"((r)[0]), "=r"((r)[1]), "=r"((r)[2]), "=r"((r)[3]) : "r"(addr))
#define MMA16816(D, a, b0, b1) \
    asm volatile("mma.sync.aligned.m16n8k16.row.col.f32.bf16.bf16.f32 " \
        "{%0,%1,%2,%3}, {%4,%5,%6,%7}, {%8,%9}, {%0,%1,%2,%3};" \
        : "+f"((D)[0]), "+f"((D)[1]), "+f"((D)[2]), "+f"((D)[3]) \
        : "r"((a)[0]), "r"((a)[1]), "r"((a)[2]), "r"((a)[3]), "r"(b0), "r"(b1))

__device__ __forceinline__ uint32_t packbf(__nv_bfloat16 a, __nv_bfloat16 b) {
    return (uint32_t)__bfloat16_as_ushort(a) | ((uint32_t)__bfloat16_as_ushort(b) << 16);
}
// split a float2 into 3 packed-bf16 terms: f = h + m + l (+ ~2^-26 residual)
__device__ __forceinline__ void split3(float2 f, uint32_t& h, uint32_t& m, uint32_t& l) {
    __nv_bfloat16 hx = __float2bfloat16(f.x); float rx = f.x - __bfloat162float(hx);
    __nv_bfloat16 mx = __float2bfloat16(rx);  rx -= __bfloat162float(mx);
    __nv_bfloat16 lx = __float2bfloat16(rx);
    __nv_bfloat16 hy = __float2bfloat16(f.y); float ry = f.y - __bfloat162float(hy);
    __nv_bfloat16 my = __float2bfloat16(ry);  ry -= __bfloat162float(my);
    __nv_bfloat16 ly = __float2bfloat16(ry);
    h = packbf(hx, hy); m = packbf(mx, my); l = packbf(lx, ly);
}

// ---------------------------------------------------------------------------
// smem layout
// Phase 1 (GEMM1): params 0..3071 | red 3072.. | stat 7168.. | W1 planes 8192..
//                  | xq planes 204800..231423
// Phase 2 (fused): W2 planes 0.. | sbf 196608.. | params 230400..231935
// ---------------------------------------------------------------------------
#define OFF_RED  3072
#define OFF_STAT 7168
#define OFF_W    8192
#define W1P      65536
#define OFF_XQ   (OFF_W + 3*W1P)          // 204800
#define XQ_PITCH 208                       // 13 x 16B: odd -> conflict-free ldmatrix

#define W2P      65536
#define OFF_SBF  (3*W2P)                   // 196608
#define SBF_BYTES 16896                    // 32 rows x 528 B
#define OFF_PAR  (OFF_SBF + 2*SBF_BYTES)   // 230400
#define SMEM_BYTES 231936

__global__ __launch_bounds__(512, 1)
void spiking_block_kernel(const float* __restrict__ x,
                          const float* __restrict__ W1,
                          const float* __restrict__ b1,
                          const float* __restrict__ g1,
                          const float* __restrict__ be1,
                          const float* __restrict__ W2,
                          const float* __restrict__ b2,
                          const float* __restrict__ g2,
                          const float* __restrict__ be2,
                          float* __restrict__ out)
{
    extern __shared__ __align__(16) char smem[];
    const int tid  = threadIdx.x;
    const int lane = tid & 31;
    const int wid  = tid >> 5;

    // ======================= PHASE 1: GEMM1 + LN -> g_h1 ====================
    {
        float* b1s  = (float*)smem;
        float* g1s  = b1s + 256;
        float* be1s = g1s + 256;
        float* red  = (float*)(smem + OFF_RED);
        float* stat = (float*)(smem + OFF_STAT);
        char*  wsm  = smem + OFF_W;
        char*  xq   = smem + OFF_XQ;

        if (tid < 256) { b1s[tid] = b1[tid]; g1s[tid] = g1[tid]; be1s[tid] = be1[tid]; }

        // Stage W1 -> 3 swizzled bf16 planes (once per block)
        #pragma unroll 4
        for (int i = 0; i < 32; i++) {
            int idx = tid + i*512;
            int h = idx >> 6, k = (idx & 63) * 2;
            float2 w = *(const float2*)(W1 + h*128 + k);
            uint32_t ph, pm, pl;
            split3(w, ph, pm, pl);
            uint32_t off = (uint32_t)h*256 + ((((uint32_t)k >> 3) ^ (h & 7)) << 4)
                         + ((k & 7) << 1);
            *(uint32_t*)(wsm + off)          = ph;
            *(uint32_t*)(wsm + W1P + off)    = pm;
            *(uint32_t*)(wsm + 2*W1P + off)  = pl;
        }
        __syncthreads();

        const int wm = wid >> 2, wn = wid & 3;
        const int brow = wn*64 + (lane & 7) + ((lane >> 4) << 3);
        const int bsel = (lane >> 3) & 1;
        const uint32_t wsm_u = smem_to_u32(wsm);
        const uint32_t abase = smem_to_u32(xq)
                             + (uint32_t)(wm*32 + (lane & 15)) * XQ_PITCH
                             + ((lane >> 4) << 4);

        for (int tt = 0; tt < 4; tt++) {
            const int rowBase = (blockIdx.x*4 + tt) * 128;
            const float* xt = x + (size_t)rowBase * DD;

            float d[2][8][4];
            #pragma unroll
            for (int mt = 0; mt < 2; mt++)
                #pragma unroll
                for (int nt = 0; nt < 8; nt++)
                    #pragma unroll
                    for (int i = 0; i < 4; i++) d[mt][nt][i] = 0.f;

            // prefetch x quarter 0 (2 float4 per thread)
            float4 pfq[2];
            #pragma unroll
            for (int i = 0; i < 2; i++) {
                int idx = tid + i*512;
                pfq[i] = *(const float4*)(xt + (idx >> 3)*DD + (idx & 7)*4);
            }

            for (int q = 0; q < 4; q++) {
                // split + store interleaved planes: [row][plane*64 + k*2]
                #pragma unroll
                for (int i = 0; i < 2; i++) {
                    int idx = tid + i*512;
                    int row = idx >> 3, c4 = idx & 7;
                    uint32_t h01, m01, l01, h23, m23, l23;
                    split3(make_float2(pfq[i].x, pfq[i].y), h01, m01, l01);
                    split3(make_float2(pfq[i].z, pfq[i].w), h23, m23, l23);
                    char* bp = xq + row*XQ_PITCH + c4*8;
                    *(uint32_t*)(bp)       = h01;  *(uint32_t*)(bp + 4)   = h23;
                    *(uint32_t*)(bp + 64)  = m01;  *(uint32_t*)(bp + 68)  = m23;
                    *(uint32_t*)(bp + 128) = l01;  *(uint32_t*)(bp + 132) = l23;
                }
                // prefetch next quarter (overlaps with MMA)
                if (q < 3) {
                    #pragma unroll
                    for (int i = 0; i < 2; i++) {
                        int idx = tid + i*512;
                        pfq[i] = *(const float4*)(xt + (idx >> 3)*DD + (q+1)*32 + (idx & 7)*4);
                    }
                }
                __syncthreads();

                #pragma unroll
                for (int ks2 = 0; ks2 < 2; ks2++) {
                    const int ks = q*2 + ks2;
                    uint32_t ah[2][4], am[2][4], al[2][4];
                    #pragma unroll
                    for (int mt = 0; mt < 2; mt++) {
                        uint32_t aa = abase + (uint32_t)mt*(16*XQ_PITCH) + ks2*32;
                        LDSM4(ah[mt], aa);
                        LDSM4(am[mt], aa + 64);
                        LDSM4(al[mt], aa + 128);
                    }
                    #pragma unroll
                    for (int np = 0; np < 4; np++) {
                        int row = brow + np*16;
                        uint32_t boff = (uint32_t)row*256 +
                                        ((((ks << 1) | bsel) ^ (row & 7)) << 4);
                        uint32_t bh[4], bm[4], bl[4];
                        LDSM4(bh, wsm_u + boff);
                        LDSM4(bm, wsm_u + W1P + boff);
                        LDSM4(bl, wsm_u + 2*W1P + boff);
                        #pragma unroll
                        for (int mt = 0; mt < 2; mt++)
                            #pragma unroll
                            for (int ns = 0; ns < 2; ns++) {
                                float* D = d[mt][np*2 + ns];
                                MMA16816(D, ah[mt], bh[ns*2], bh[ns*2+1]);  // hh
                                MMA16816(D, ah[mt], bm[ns*2], bm[ns*2+1]);  // hm
                                MMA16816(D, am[mt], bh[ns*2], bh[ns*2+1]);  // mh
                                MMA16816(D, am[mt], bm[ns*2], bm[ns*2+1]);  // mm
                                MMA16816(D, ah[mt], bl[ns*2], bl[ns*2+1]);  // hl
                                MMA16816(D, al[mt], bh[ns*2], bh[ns*2+1]);  // lh
                            }
                    }
                }
                __syncthreads();
            }

            // ---- epilogue: bias + LN + store (proven R6 code) ----
            float psum[2][2] = {{0.f,0.f},{0.f,0.f}}, psq[2][2] = {{0.f,0.f},{0.f,0.f}};
            #pragma unroll
            for (int mt = 0; mt < 2; mt++)
                #pragma unroll
                for (int nt = 0; nt < 8; nt++) {
                    int col = wn*64 + nt*8 + (lane & 3)*2;
                    float bx = b1s[col], by = b1s[col+1];
                    float* D = d[mt][nt];
                    D[0] += bx; D[1] += by; D[2] += bx; D[3] += by;
                    psum[mt][0] += D[0] + D[1]; psq[mt][0] += D[0]*D[0] + D[1]*D[1];
                    psum[mt][1] += D[2] + D[3]; psq[mt][1] += D[2]*D[2] + D[3]*D[3];
                }
            #pragma unroll
            for (int mt = 0; mt < 2; mt++)
                #pragma unroll
                for (int rh = 0; rh < 2; rh++) {
                    #pragma unroll
                    for (int o = 1; o <= 2; o <<= 1) {
                        psum[mt][rh] += __shfl_xor_sync(0xffffffffu, psum[mt][rh], o);
                        psq[mt][rh]  += __shfl_xor_sync(0xffffffffu, psq[mt][rh],  o);
                    }
                    if ((lane & 3) == 0) {
                        int r = wm*32 + mt*16 + rh*8 + (lane >> 2);
                        red[r*8 + wn*2 + 0] = psum[mt][rh];
                        red[r*8 + wn*2 + 1] = psq[mt][rh];
                    }
                }
            __syncthreads();
            if (tid < 128) {
                float s = red[tid*8+0] + red[tid*8+2] + red[tid*8+4] + red[tid*8+6];
                float qq = red[tid*8+1] + red[tid*8+3] + red[tid*8+5] + red[tid*8+7];
                float mean = s * (1.f/256.f);
                float var  = fmaxf(qq * (1.f/256.f) - mean*mean, 0.f) + 1e-5f;
                float inv  = rsqrtf(var);
                inv = inv * (1.5f - 0.5f * var * inv * inv);   // fp32-exact rsqrt
                stat[tid*2]   = mean;
                stat[tid*2+1] = inv;
            }
            __syncthreads();

            #pragma unroll
            for (int mt = 0; mt < 2; mt++) {
                int r0 = wm*32 + mt*16 + (lane >> 2);
                float mean0 = stat[r0*2],     inv0 = stat[r0*2+1];
                float mean1 = stat[(r0+8)*2], inv1 = stat[(r0+8)*2+1];
                float* o0 = g_h1 + (size_t)(rowBase + r0) * HH;
                float* o1 = o0 + 8*HH;
                #pragma unroll
                for (int nt = 0; nt < 8; nt++) {
                    int col = wn*64 + nt*8 + (lane & 3)*2;
                    float gx = g1s[col], gy = g1s[col+1];
                    float ex = be1s[col], ey = be1s[col+1];
                    float* D = d[mt][nt];
                    float2 w0, w1;
                    w0.x = (D[0] - mean0) * inv0 * gx + ex;
                    w0.y = (D[1] - mean0) * inv0 * gy + ey;
                    w1.x = (D[2] - mean1) * inv1 * gx + ex;
                    w1.y = (D[3] - mean1) * inv1 * gy + ey;
                    *(float2*)(o0 + col) = w0;
                    *(float2*)(o1 + col) = w1;
                }
            }
            __syncthreads();   // before next tile reuses red/stat/xq
        }
    }
    __syncthreads();

    // ====== PHASE 2: LIF1 -> GEMM2(HMMA, W2 3-plane) -> LN -> LIF2 + res ====
    {
        char*  wsm  = smem;                              // 3 W2 planes
        float* b2s  = (float*)(smem + OFF_PAR);
        float* g2s  = b2s + 128;
        float* be2s = g2s + 128;

        const int half = tid >> 8;
        const int htid = tid & 255;
        const int w8   = (tid >> 5) & 7;                 // warp within half
        char*  sbf = smem + OFF_SBF + half * SBF_BYTES;  // [32 t][528 B] bf16
        float* os  = (float*)sbf;                        // alias [32][128] f32

        const int b = blockIdx.x * 2 + half;
        const float* h1base = g_h1 + (size_t)b * (TT * HH);
        const size_t xbase  = (size_t)b * (TT * DD);

        if (tid < 128) { b2s[tid] = b2[tid]; g2s[tid] = g2[tid]; be2s[tid] = be2[tid]; }

        // prefetch chunk 0 (L2-hot: written by this block in phase 1)
        float pf[32];
        #pragma unroll
        for (int t = 0; t < 32; t++) pf[t] = h1base[t*HH + htid];

        // Stage W2 -> 3 swizzled bf16 planes ([d=128 rows][512 B])
        #pragma unroll 4
        for (int i = 0; i < 32; i++) {
            int idx = tid + i*512;
            int dd2 = idx >> 7, k = (idx & 127) * 2;
            float2 w = *(const float2*)(W2 + dd2*256 + k);
            uint32_t ph, pm, pl;
            split3(w, ph, pm, pl);
            uint32_t off = (uint32_t)dd2*512 + ((((uint32_t)k >> 3) ^ (dd2 & 7)) << 4)
                         + ((k & 7) << 1);
            *(uint32_t*)(wsm + off)         = ph;
            *(uint32_t*)(wsm + W2P + off)   = pm;
            *(uint32_t*)(wsm + 2*W2P + off) = pl;
        }
        __syncthreads();

        // warp tiling: M=32 t (2 mtiles), N=16 d (w8*16), 5 LDSM : 12 MMA / ks
        const uint32_t wsm_u = smem_to_u32(wsm);
        const uint32_t abase = smem_to_u32(sbf) + (uint32_t)(lane & 15)*528
                             + ((lane >> 4) << 4);
        const int brow0 = w8*16 + (lane & 7) + ((lane >> 4) << 3);
        const int bsel  = (lane >> 3) & 1;

        float v1 = 0.f, v2 = 0.f;

        for (int c = 0; c < 8; c++) {
            // ---- LIF1: spikes as constant bf16 bits ----
            {
                float v = v1;
                #pragma unroll
                for (int t = 0; t < 32; t++) {
                    float hm = v + (pf[t] - v) * 0.5f;
                    *(uint16_t*)(sbf + t*528 + htid*2) = (hm >= 1.f) ? 0x3F80u : 0u;
                    v = (hm >= 1.f) ? 0.f : hm;
                }
                v1 = v;
            }
            __syncthreads();

            if (c + 1 < 8) {
                const float* hn = h1base + (size_t)(c+1) * 32 * HH;
                #pragma unroll
                for (int t = 0; t < 32; t++) pf[t] = hn[t*HH + htid];
            }

            // ---- GEMM2 ----
            float D[2][2][4];
            #pragma unroll
            for (int mt = 0; mt < 2; mt++)
                #pragma unroll
                for (int nt = 0; nt < 2; nt++) {
                    int col = w8*16 + nt*8 + (lane & 3)*2;
                    D[mt][nt][0] = b2s[col]; D[mt][nt][1] = b2s[col+1];
                    D[mt][nt][2] = b2s[col]; D[mt][nt][3] = b2s[col+1];
                }
            for (int ks = 0; ks < 16; ks++) {
                uint32_t a0[4], a1[4];
                LDSM4(a0, abase + ks*32);
                LDSM4(a1, abase + 16*528 + ks*32);
                uint32_t boff = (uint32_t)brow0*512 +
                                ((((ks << 1) | bsel) ^ (brow0 & 7)) << 4);
                #pragma unroll
                for (int p = 0; p < 3; p++) {
                    uint32_t bb[4];
                    LDSM4(bb, wsm_u + p*W2P + boff);
                    MMA16816(D[0][0], a0, bb[0], bb[1]);
                    MMA16816(D[0][1], a0, bb[2], bb[3]);
                    MMA16816(D[1][0], a1, bb[0], bb[1]);
                    MMA16816(D[1][1], a1, bb[2], bb[3]);
                }
            }
            __syncthreads();   // reads of sbf done before os (alias) writes

            // ---- store D -> os[32][128] ----
            {
                int r0 = lane >> 2;
                #pragma unroll
                for (int mt = 0; mt < 2; mt++)
                    #pragma unroll
                    for (int nt = 0; nt < 2; nt++) {
                        int col = w8*16 + nt*8 + (lane & 3)*2;
                        *(float2*)(os + (mt*16 + r0)*128 + col)
                            = make_float2(D[mt][nt][0], D[mt][nt][1]);
                        *(float2*)(os + (mt*16 + r0 + 8)*128 + col)
                            = make_float2(D[mt][nt][2], D[mt][nt][3]);
                    }
            }
            __syncthreads();

            // ---- LayerNorm over D=128 per row (8 warps x 4 rows) ----
            #pragma unroll
            for (int rr = 0; rr < 4; rr++) {
                int row = w8*4 + rr;
                float v[4];
                #pragma unroll
                for (int i = 0; i < 4; i++) v[i] = os[row*128 + lane + 32*i];
                float sum = 0.f, sq = 0.f;
                #pragma unroll
                for (int i = 0; i < 4; i++) { sum += v[i]; sq += v[i]*v[i]; }
                #pragma unroll
                for (int o = 16; o; o >>= 1) {
                    sum += __shfl_xor_sync(0xffffffffu, sum, o);
                    sq  += __shfl_xor_sync(0xffffffffu, sq,  o);
                }
                float mean = sum * (1.f/128.f);
                float var  = fmaxf(sq * (1.f/128.f) - mean*mean, 0.f) + 1e-5f;
                float inv  = rsqrtf(var);
                inv = inv * (1.5f - 0.5f * var * inv * inv);
                #pragma unroll
                for (int i = 0; i < 4; i++) {
                    int dd2 = lane + 32*i;
                    os[row*128 + dd2] = (v[i] - mean) * inv * g2s[dd2] + be2s[dd2];
                }
            }
            __syncthreads();

            // ---- LIF2 + residual ----
            if (htid < 128) {
                const float* xp = x   + xbase + (size_t)c * 32 * DD + htid;
                float*       op = out + xbase + (size_t)c * 32 * DD + htid;
                float v = v2;
                #pragma unroll
                for (int t = 0; t < 32; t++) {
                    float hm = v + (os[t*128 + htid] - v) * 0.5f;
                    float s  = (hm >= 1.f) ? 1.f : 0.f;
                    v = (hm >= 1.f) ? 0.f : hm;
                    op[(size_t)t * DD] = xp[(size_t)t * DD] + s;
                }
                v2 = v;
            }
            __syncthreads();   // before next chunk overwrites sbf/os
        }
    }
}

// ---------------------------------------------------------------------------
extern "C" void kernel_launch(void* const* d_in, const int* in_sizes, int n_in,
                              void* d_out, int out_size)
{
    const float* x   = (const float*)d_in[0];
    const float* W1  = (const float*)d_in[1];
    const float* b1  = (const float*)d_in[2];
    const float* g1  = (const float*)d_in[3];
    const float* be1 = (const float*)d_in[4];
    const float* W2  = (const float*)d_in[5];
    const float* b2  = (const float*)d_in[6];
    const float* g2  = (const float*)d_in[7];
    const float* be2 = (const float*)d_in[8];
    float* out = (float*)d_out;

    (void)in_sizes; (void)n_in; (void)out_size;

    cudaFuncSetAttribute(spiking_block_kernel,
                         cudaFuncAttributeMaxDynamicSharedMemorySize, SMEM_BYTES);

    spiking_block_kernel<<<BB/2, 512, SMEM_BYTES>>>(x, W1, b1, g1, be1,
                                                    W2, b2, g2, be2, out);
}

// round 9
// speedup vs baseline: 2.2732x; 1.0693x over previous
#include <cuda_runtime.h>
#include <cuda_bf16.h>
#include <cstdint>

// Problem dims (fixed by the dataset)
#define BB 256
#define TT 256
#define DD 128
#define HH 256
#define NROWS (BB*TT)          // 65536

// Scratch: h1 (post-LN, pre-LIF1) [B,T,H]
__device__ __align__(16) float g_h1[(size_t)NROWS * HH];   // 67 MB

// ---------------------------------------------------------------------------
// mma.sync / ldmatrix helpers (family-portable; NO tcgen05 — harness PTX
// target is plain sm_103, arch-specific features are rejected by ptxas)
// ---------------------------------------------------------------------------
__device__ __forceinline__ uint32_t smem_to_u32(const void* p) {
    uint32_t a;
    asm("{ .reg .u64 t; cvta.to.shared.u64 t, %1; cvt.u32.u64 %0, t; }"
        : "=r"(a) : "l"(p));
    return a;
}
#define LDSM4(r, addr) \
    asm volatile("ldmatrix.sync.aligned.m8n8.x4.shared.b16 {%0,%1,%2,%3}, [%4];" \
        : "=r"((r)[0]), "=r"((r)[1]), "=r"((r)[2]), "=r"((r)[3]) : "r"(addr))
#define MMA16816(D, a, b0, b1) \
    asm volatile("mma.sync.aligned.m16n8k16.row.col.f32.bf16.bf16.f32 " \
        "{%0,%1,%2,%3}, {%4,%5,%6,%7}, {%8,%9}, {%0,%1,%2,%3};" \
        : "+f"((D)[0]), "+f"((D)[1]), "+f"((D)[2]), "+f"((D)[3]) \
        : "r"((a)[0]), "r"((a)[1]), "r"((a)[2]), "r"((a)[3]), "r"(b0), "r"(b1))
// named barriers: group-scope sync (ids 1-7; 0 is __syncthreads)
#define BARN(id, cnt) asm volatile("bar.sync %0, %1;" :: "r"(id), "r"(cnt) : "memory")

__device__ __forceinline__ uint32_t packbf(__nv_bfloat16 a, __nv_bfloat16 b) {
    return (uint32_t)__bfloat16_as_ushort(a) | ((uint32_t)__bfloat16_as_ushort(b) << 16);
}
// split a float2 into 3 packed-bf16 terms: f = h + m + l (+ ~2^-26 residual)
__device__ __forceinline__ void split3(float2 f, uint32_t& h, uint32_t& m, uint32_t& l) {
    __nv_bfloat16 hx = __float2bfloat16(f.x); float rx = f.x - __bfloat162float(hx);
    __nv_bfloat16 mx = __float2bfloat16(rx);  rx -= __bfloat162float(mx);
    __nv_bfloat16 lx = __float2bfloat16(rx);
    __nv_bfloat16 hy = __float2bfloat16(f.y); float ry = f.y - __bfloat162float(hy);
    __nv_bfloat16 my = __float2bfloat16(ry);  ry -= __bfloat162float(my);
    __nv_bfloat16 ly = __float2bfloat16(ry);
    h = packbf(hx, hy); m = packbf(mx, my); l = packbf(lx, ly);
}

// ---------------------------------------------------------------------------
// smem layout (unchanged from R8)
// ---------------------------------------------------------------------------
#define OFF_RED  3072
#define OFF_STAT 7168
#define OFF_W    8192
#define W1P      65536
#define OFF_XQ   (OFF_W + 3*W1P)          // 204800
#define XQ_PITCH 208                       // 13 x 16B: odd -> conflict-free ldmatrix

#define W2P      65536
#define OFF_SBF  (3*W2P)                   // 196608
#define SBF_BYTES 16896                    // 32 rows x 528 B
#define OFF_PAR  (OFF_SBF + 2*SBF_BYTES)   // 230400
#define SMEM_BYTES 231936

__global__ __launch_bounds__(512, 1)
void spiking_block_kernel(const float* __restrict__ x,
                          const float* __restrict__ W1,
                          const float* __restrict__ b1,
                          const float* __restrict__ g1,
                          const float* __restrict__ be1,
                          const float* __restrict__ W2,
                          const float* __restrict__ b2,
                          const float* __restrict__ g2,
                          const float* __restrict__ be2,
                          float* __restrict__ out)
{
    extern __shared__ __align__(16) char smem[];
    const int tid  = threadIdx.x;
    const int lane = tid & 31;
    const int wid  = tid >> 5;

    // ======================= PHASE 1: GEMM1 + LN -> g_h1 ====================
    {
        float* b1s  = (float*)smem;
        float* g1s  = b1s + 256;
        float* be1s = g1s + 256;
        float* red  = (float*)(smem + OFF_RED);
        float* stat = (float*)(smem + OFF_STAT);
        char*  wsm  = smem + OFF_W;
        char*  xq   = smem + OFF_XQ;

        if (tid < 256) { b1s[tid] = b1[tid]; g1s[tid] = g1[tid]; be1s[tid] = be1[tid]; }

        // Stage W1 -> 3 swizzled bf16 planes (once per block)
        #pragma unroll 4
        for (int i = 0; i < 32; i++) {
            int idx = tid + i*512;
            int h = idx >> 6, k = (idx & 63) * 2;
            float2 w = *(const float2*)(W1 + h*128 + k);
            uint32_t ph, pm, pl;
            split3(w, ph, pm, pl);
            uint32_t off = (uint32_t)h*256 + ((((uint32_t)k >> 3) ^ (h & 7)) << 4)
                         + ((k & 7) << 1);
            *(uint32_t*)(wsm + off)          = ph;
            *(uint32_t*)(wsm + W1P + off)    = pm;
            *(uint32_t*)(wsm + 2*W1P + off)  = pl;
        }
        __syncthreads();

        const int wm = wid >> 2, wn = wid & 3;
        const int gtid = tid & 127;            // thread within wm-group
        const int gbar = 4 + wm;               // named barrier id for this group
        const int brow = wn*64 + (lane & 7) + ((lane >> 4) << 3);
        const int bsel = (lane >> 3) & 1;
        const uint32_t wsm_u = smem_to_u32(wsm);
        const uint32_t abase = smem_to_u32(xq)
                             + (uint32_t)(wm*32 + (lane & 15)) * XQ_PITCH
                             + ((lane >> 4) << 4);

        for (int tt = 0; tt < 4; tt++) {
            const int rowBase = (blockIdx.x*4 + tt) * 128;
            const float* xt = x + (size_t)rowBase * DD;

            float d[2][8][4];
            #pragma unroll
            for (int mt = 0; mt < 2; mt++)
                #pragma unroll
                for (int nt = 0; nt < 8; nt++)
                    #pragma unroll
                    for (int i = 0; i < 4; i++) d[mt][nt][i] = 0.f;

            // prefetch x quarter 0 — group wm stages ONLY its own 32 rows
            float4 pfq[2];
            #pragma unroll
            for (int i = 0; i < 2; i++) {
                int idx = gtid + i*128;                       // 256 f4 per group
                int row = wm*32 + (idx >> 3);
                pfq[i] = *(const float4*)(xt + row*DD + (idx & 7)*4);
            }

            for (int q = 0; q < 4; q++) {
                // split + store own rows: [row][plane*64 + k*2]
                #pragma unroll
                for (int i = 0; i < 2; i++) {
                    int idx = gtid + i*128;
                    int row = wm*32 + (idx >> 3), c4 = idx & 7;
                    uint32_t h01, m01, l01, h23, m23, l23;
                    split3(make_float2(pfq[i].x, pfq[i].y), h01, m01, l01);
                    split3(make_float2(pfq[i].z, pfq[i].w), h23, m23, l23);
                    char* bp = xq + row*XQ_PITCH + c4*8;
                    *(uint32_t*)(bp)       = h01;  *(uint32_t*)(bp + 4)   = h23;
                    *(uint32_t*)(bp + 64)  = m01;  *(uint32_t*)(bp + 68)  = m23;
                    *(uint32_t*)(bp + 128) = l01;  *(uint32_t*)(bp + 132) = l23;
                }
                // prefetch next quarter (overlaps with MMA)
                if (q < 3) {
                    #pragma unroll
                    for (int i = 0; i < 2; i++) {
                        int idx = gtid + i*128;
                        int row = wm*32 + (idx >> 3);
                        pfq[i] = *(const float4*)(xt + row*DD + (q+1)*32 + (idx & 7)*4);
                    }
                }
                BARN(gbar, 128);   // group-scope: own rows staged

                #pragma unroll
                for (int ks2 = 0; ks2 < 2; ks2++) {
                    const int ks = q*2 + ks2;
                    uint32_t ah[2][4], am[2][4], al[2][4];
                    #pragma unroll
                    for (int mt = 0; mt < 2; mt++) {
                        uint32_t aa = abase + (uint32_t)mt*(16*XQ_PITCH) + ks2*32;
                        LDSM4(ah[mt], aa);
                        LDSM4(am[mt], aa + 64);
                        LDSM4(al[mt], aa + 128);
                    }
                    #pragma unroll
                    for (int np = 0; np < 4; np++) {
                        int row = brow + np*16;
                        uint32_t boff = (uint32_t)row*256 +
                                        ((((ks << 1) | bsel) ^ (row & 7)) << 4);
                        uint32_t bh[4], bm[4], bl[4];
                        LDSM4(bh, wsm_u + boff);
                        LDSM4(bm, wsm_u + W1P + boff);
                        LDSM4(bl, wsm_u + 2*W1P + boff);
                        #pragma unroll
                        for (int mt = 0; mt < 2; mt++)
                            #pragma unroll
                            for (int ns = 0; ns < 2; ns++) {
                                float* D = d[mt][np*2 + ns];
                                MMA16816(D, ah[mt], bh[ns*2], bh[ns*2+1]);  // hh
                                MMA16816(D, ah[mt], bm[ns*2], bm[ns*2+1]);  // hm
                                MMA16816(D, am[mt], bh[ns*2], bh[ns*2+1]);  // mh
                                MMA16816(D, am[mt], bm[ns*2], bm[ns*2+1]);  // mm
                                MMA16816(D, ah[mt], bl[ns*2], bl[ns*2+1]);  // hl
                                MMA16816(D, al[mt], bh[ns*2], bh[ns*2+1]);  // lh
                            }
                    }
                }
                BARN(gbar, 128);   // group-scope: MMA reads done before overwrite
            }

            // ---- epilogue: bias + LN + store ----
            float psum[2][2] = {{0.f,0.f},{0.f,0.f}}, psq[2][2] = {{0.f,0.f},{0.f,0.f}};
            #pragma unroll
            for (int mt = 0; mt < 2; mt++)
                #pragma unroll
                for (int nt = 0; nt < 8; nt++) {
                    int col = wn*64 + nt*8 + (lane & 3)*2;
                    float bx = b1s[col], by = b1s[col+1];
                    float* D = d[mt][nt];
                    D[0] += bx; D[1] += by; D[2] += bx; D[3] += by;
                    psum[mt][0] += D[0] + D[1]; psq[mt][0] += D[0]*D[0] + D[1]*D[1];
                    psum[mt][1] += D[2] + D[3]; psq[mt][1] += D[2]*D[2] + D[3]*D[3];
                }
            #pragma unroll
            for (int mt = 0; mt < 2; mt++)
                #pragma unroll
                for (int rh = 0; rh < 2; rh++) {
                    #pragma unroll
                    for (int o = 1; o <= 2; o <<= 1) {
                        psum[mt][rh] += __shfl_xor_sync(0xffffffffu, psum[mt][rh], o);
                        psq[mt][rh]  += __shfl_xor_sync(0xffffffffu, psq[mt][rh],  o);
                    }
                    if ((lane & 3) == 0) {
                        int r = wm*32 + mt*16 + rh*8 + (lane >> 2);
                        red[r*8 + wn*2 + 0] = psum[mt][rh];
                        red[r*8 + wn*2 + 1] = psq[mt][rh];
                    }
                }
            __syncthreads();
            if (tid < 128) {
                float s = red[tid*8+0] + red[tid*8+2] + red[tid*8+4] + red[tid*8+6];
                float qq = red[tid*8+1] + red[tid*8+3] + red[tid*8+5] + red[tid*8+7];
                float mean = s * (1.f/256.f);
                float var  = fmaxf(qq * (1.f/256.f) - mean*mean, 0.f) + 1e-5f;
                float inv  = rsqrtf(var);
                inv = inv * (1.5f - 0.5f * var * inv * inv);   // fp32-exact rsqrt
                stat[tid*2]   = mean;
                stat[tid*2+1] = inv;
            }
            __syncthreads();

            #pragma unroll
            for (int mt = 0; mt < 2; mt++) {
                int r0 = wm*32 + mt*16 + (lane >> 2);
                float mean0 = stat[r0*2],     inv0 = stat[r0*2+1];
                float mean1 = stat[(r0+8)*2], inv1 = stat[(r0+8)*2+1];
                float* o0 = g_h1 + (size_t)(rowBase + r0) * HH;
                float* o1 = o0 + 8*HH;
                #pragma unroll
                for (int nt = 0; nt < 8; nt++) {
                    int col = wn*64 + nt*8 + (lane & 3)*2;
                    float gx = g1s[col], gy = g1s[col+1];
                    float ex = be1s[col], ey = be1s[col+1];
                    float* D = d[mt][nt];
                    float2 w0, w1;
                    w0.x = (D[0] - mean0) * inv0 * gx + ex;
                    w0.y = (D[1] - mean0) * inv0 * gy + ey;
                    w1.x = (D[2] - mean1) * inv1 * gx + ex;
                    w1.y = (D[3] - mean1) * inv1 * gy + ey;
                    *(float2*)(o0 + col) = w0;
                    *(float2*)(o1 + col) = w1;
                }
            }
            __syncthreads();   // before next tile reuses red/stat/xq
        }
    }
    __syncthreads();

    // ====== PHASE 2: LIF1 -> GEMM2(HMMA, W2 3-plane) -> LN -> LIF2 + res ====
    {
        char*  wsm  = smem;                              // 3 W2 planes
        float* b2s  = (float*)(smem + OFF_PAR);
        float* g2s  = b2s + 128;
        float* be2s = g2s + 128;

        const int half = tid >> 8;
        const int htid = tid & 255;
        const int w8   = (tid >> 5) & 7;                 // warp within half
        const int hbar = 1 + half;                       // named barrier per half
        char*  sbf = smem + OFF_SBF + half * SBF_BYTES;  // [32 t][528 B] bf16
        float* os  = (float*)sbf;                        // alias [32][128] f32

        const int b = blockIdx.x * 2 + half;
        const float* h1base = g_h1 + (size_t)b * (TT * HH);
        const size_t xbase  = (size_t)b * (TT * DD);

        if (tid < 128) { b2s[tid] = b2[tid]; g2s[tid] = g2[tid]; be2s[tid] = be2[tid]; }

        // prefetch chunk 0 (L2-hot: written by this block in phase 1)
        float pf[32];
        #pragma unroll
        for (int t = 0; t < 32; t++) pf[t] = h1base[t*HH + htid];

        // Stage W2 -> 3 swizzled bf16 planes ([d=128 rows][512 B])
        #pragma unroll 4
        for (int i = 0; i < 32; i++) {
            int idx = tid + i*512;
            int dd2 = idx >> 7, k = (idx & 127) * 2;
            float2 w = *(const float2*)(W2 + dd2*256 + k);
            uint32_t ph, pm, pl;
            split3(w, ph, pm, pl);
            uint32_t off = (uint32_t)dd2*512 + ((((uint32_t)k >> 3) ^ (dd2 & 7)) << 4)
                         + ((k & 7) << 1);
            *(uint32_t*)(wsm + off)         = ph;
            *(uint32_t*)(wsm + W2P + off)   = pm;
            *(uint32_t*)(wsm + 2*W2P + off) = pl;
        }
        __syncthreads();   // W2 planes + params visible to both halves

        // warp tiling: M=32 t (2 mtiles), N=16 d (w8*16), 5 LDSM : 12 MMA / ks
        const uint32_t wsm_u = smem_to_u32(wsm);
        const uint32_t abase = smem_to_u32(sbf) + (uint32_t)(lane & 15)*528
                             + ((lane >> 4) << 4);
        const int brow0 = w8*16 + (lane & 7) + ((lane >> 4) << 3);
        const int bsel  = (lane >> 3) & 1;

        float v1 = 0.f, v2 = 0.f;

        for (int c = 0; c < 8; c++) {
            // ---- LIF1: spikes as constant bf16 bits ----
            {
                float v = v1;
                #pragma unroll
                for (int t = 0; t < 32; t++) {
                    float hm = v + (pf[t] - v) * 0.5f;
                    *(uint16_t*)(sbf + t*528 + htid*2) = (hm >= 1.f) ? 0x3F80u : 0u;
                    v = (hm >= 1.f) ? 0.f : hm;
                }
                v1 = v;
            }
            BARN(hbar, 256);

            if (c + 1 < 8) {
                const float* hn = h1base + (size_t)(c+1) * 32 * HH;
                #pragma unroll
                for (int t = 0; t < 32; t++) pf[t] = hn[t*HH + htid];
            }

            // ---- GEMM2 ----
            float D[2][2][4];
            #pragma unroll
            for (int mt = 0; mt < 2; mt++)
                #pragma unroll
                for (int nt = 0; nt < 2; nt++) {
                    int col = w8*16 + nt*8 + (lane & 3)*2;
                    D[mt][nt][0] = b2s[col]; D[mt][nt][1] = b2s[col+1];
                    D[mt][nt][2] = b2s[col]; D[mt][nt][3] = b2s[col+1];
                }
            for (int ks = 0; ks < 16; ks++) {
                uint32_t a0[4], a1[4];
                LDSM4(a0, abase + ks*32);
                LDSM4(a1, abase + 16*528 + ks*32);
                uint32_t boff = (uint32_t)brow0*512 +
                                ((((ks << 1) | bsel) ^ (brow0 & 7)) << 4);
                #pragma unroll
                for (int p = 0; p < 3; p++) {
                    uint32_t bb[4];
                    LDSM4(bb, wsm_u + p*W2P + boff);
                    MMA16816(D[0][0], a0, bb[0], bb[1]);
                    MMA16816(D[0][1], a0, bb[2], bb[3]);
                    MMA16816(D[1][0], a1, bb[0], bb[1]);
                    MMA16816(D[1][1], a1, bb[2], bb[3]);
                }
            }
            BARN(hbar, 256);   // reads of sbf done before os (alias) writes

            // ---- store D -> os[32][128] ----
            {
                int r0 = lane >> 2;
                #pragma unroll
                for (int mt = 0; mt < 2; mt++)
                    #pragma unroll
                    for (int nt = 0; nt < 2; nt++) {
                        int col = w8*16 + nt*8 + (lane & 3)*2;
                        *(float2*)(os + (mt*16 + r0)*128 + col)
                            = make_float2(D[mt][nt][0], D[mt][nt][1]);
                        *(float2*)(os + (mt*16 + r0 + 8)*128 + col)
                            = make_float2(D[mt][nt][2], D[mt][nt][3]);
                    }
            }
            BARN(hbar, 256);

            // ---- LayerNorm over D=128 per row (8 warps x 4 rows) ----
            #pragma unroll
            for (int rr = 0; rr < 4; rr++) {
                int row = w8*4 + rr;
                float v[4];
                #pragma unroll
                for (int i = 0; i < 4; i++) v[i] = os[row*128 + lane + 32*i];
                float sum = 0.f, sq = 0.f;
                #pragma unroll
                for (int i = 0; i < 4; i++) { sum += v[i]; sq += v[i]*v[i]; }
                #pragma unroll
                for (int o = 16; o; o >>= 1) {
                    sum += __shfl_xor_sync(0xffffffffu, sum, o);
                    sq  += __shfl_xor_sync(0xffffffffu, sq,  o);
                }
                float mean = sum * (1.f/128.f);
                float var  = fmaxf(sq * (1.f/128.f) - mean*mean, 0.f) + 1e-5f;
                float inv  = rsqrtf(var);
                inv = inv * (1.5f - 0.5f * var * inv * inv);
                #pragma unroll
                for (int i = 0; i < 4; i++) {
                    int dd2 = lane + 32*i;
                    os[row*128 + dd2] = (v[i] - mean) * inv * g2s[dd2] + be2s[dd2];
                }
            }
            BARN(hbar, 256);

            // ---- LIF2 + residual ----
            if (htid < 128) {
                const float* xp = x   + xbase + (size_t)c * 32 * DD + htid;
                float*       op = out + xbase + (size_t)c * 32 * DD + htid;
                float v = v2;
                #pragma unroll
                for (int t = 0; t < 32; t++) {
                    float hm = v + (os[t*128 + htid] - v) * 0.5f;
                    float s  = (hm >= 1.f) ? 1.f : 0.f;
                    v = (hm >= 1.f) ? 0.f : hm;
                    op[(size_t)t * DD] = xp[(size_t)t * DD] + s;
                }
                v2 = v;
            }
            BARN(hbar, 256);   // before next chunk overwrites sbf/os
        }
    }
}

// ---------------------------------------------------------------------------
extern "C" void kernel_launch(void* const* d_in, const int* in_sizes, int n_in,
                              void* d_out, int out_size)
{
    const float* x   = (const float*)d_in[0];
    const float* W1  = (const float*)d_in[1];
    const float* b1  = (const float*)d_in[2];
    const float* g1  = (const float*)d_in[3];
    const float* be1 = (const float*)d_in[4];
    const float* W2  = (const float*)d_in[5];
    const float* b2  = (const float*)d_in[6];
    const float* g2  = (const float*)d_in[7];
    const float* be2 = (const float*)d_in[8];
    float* out = (float*)d_out;

    (void)in_sizes; (void)n_in; (void)out_size;

    cudaFuncSetAttribute(spiking_block_kernel,
                         cudaFuncAttributeMaxDynamicSharedMemorySize, SMEM_BYTES);

    spiking_block_kernel<<<BB/2, 512, SMEM_BYTES>>>(x, W1, b1, g1, be1,
                                                    W2, b2, g2, be2, out);
}